// round 3
// baseline (speedup 1.0000x reference)
#include <cuda_runtime.h>
#include <cuda_bf16.h>
#include <cstdint>

#define ROWS_ 8192

// ---------------- device scratch ----------------
__device__ float g_x    [ROWS_*256];
__device__ float g_qkv  [ROWS_*768];
__device__ float g_att  [ROWS_*256];
__device__ float g_ff   [ROWS_*512];
__device__ float g_tmp  [ROWS_*256];
__device__ float g_bb   [32*64];
__device__ float g_eproj[ROWS_*256];
__device__ float g_xin  [ROWS_*256];
__device__ float g_gin  [ROWS_*1024];
__device__ float g_hall [ROWS_*256];
__device__ float g_hp   [ROWS_*256];

__device__ __forceinline__ float sigf(float x) {
    return __fdividef(1.f, 1.f + __expf(-x));
}
__device__ __forceinline__ float tanh_fast(float x) {
    float xx = fminf(fmaxf(x, -15.f), 15.f);
    float e  = __expf(2.f * xx);
    return __fdividef(e - 1.f, e + 1.f);
}

// ---------------- SGEMM: C[M,N] = A[M,K] @ W[N,K]^T + bias (+bias2), opt ReLU
// M,N multiples of 128; K multiple of 8.
template<int ACT>
__global__ __launch_bounds__(256, 2) void sgemm_tn(
    const float* __restrict__ A, const float* __restrict__ W,
    const float* __restrict__ bias, const float* __restrict__ bias2,
    float* __restrict__ C, int M, int N, int K)
{
    __shared__ float As[8][128];
    __shared__ float Ws[8][128];
    int tid = threadIdx.x;
    int m0 = blockIdx.y * 128;
    int n0 = blockIdx.x * 128;
    int lr = tid >> 1;
    int lk = (tid & 1) * 4;
    const float* Aptr = A + (size_t)(m0 + lr) * K + lk;
    const float* Wptr = W + (size_t)(n0 + lr) * K + lk;
    int tx = tid & 15, ty = tid >> 4;

    float acc[8][8];
#pragma unroll
    for (int i = 0; i < 8; i++)
#pragma unroll
        for (int j = 0; j < 8; j++) acc[i][j] = 0.f;

    float4 a4 = *(const float4*)Aptr;
    float4 w4 = *(const float4*)Wptr;

    for (int kt = 0; kt < K; kt += 8) {
        As[lk+0][lr] = a4.x; As[lk+1][lr] = a4.y; As[lk+2][lr] = a4.z; As[lk+3][lr] = a4.w;
        Ws[lk+0][lr] = w4.x; Ws[lk+1][lr] = w4.y; Ws[lk+2][lr] = w4.z; Ws[lk+3][lr] = w4.w;
        __syncthreads();
        if (kt + 8 < K) {
            a4 = *(const float4*)(Aptr + kt + 8);
            w4 = *(const float4*)(Wptr + kt + 8);
        }
#pragma unroll
        for (int kk = 0; kk < 8; kk++) {
            float4 a0 = *(const float4*)&As[kk][ty*8];
            float4 a1 = *(const float4*)&As[kk][ty*8+4];
            float4 b0 = *(const float4*)&Ws[kk][tx*8];
            float4 b1 = *(const float4*)&Ws[kk][tx*8+4];
            float a[8] = {a0.x,a0.y,a0.z,a0.w,a1.x,a1.y,a1.z,a1.w};
            float b[8] = {b0.x,b0.y,b0.z,b0.w,b1.x,b1.y,b1.z,b1.w};
#pragma unroll
            for (int i = 0; i < 8; i++)
#pragma unroll
                for (int j = 0; j < 8; j++) acc[i][j] = fmaf(a[i], b[j], acc[i][j]);
        }
        __syncthreads();
    }

#pragma unroll
    for (int i = 0; i < 8; i++) {
        size_t m = (size_t)(m0 + ty*8 + i);
        float* crow = C + m * N + n0 + tx*8;
#pragma unroll
        for (int jj = 0; jj < 2; jj++) {
            int nb = n0 + tx*8 + jj*4;
            float4 bv = *(const float4*)(bias + nb);
            if (bias2) {
                float4 b2 = *(const float4*)(bias2 + nb);
                bv.x += b2.x; bv.y += b2.y; bv.z += b2.z; bv.w += b2.w;
            }
            float4 r;
            r.x = acc[i][jj*4+0] + bv.x;
            r.y = acc[i][jj*4+1] + bv.y;
            r.z = acc[i][jj*4+2] + bv.z;
            r.w = acc[i][jj*4+3] + bv.w;
            if (ACT == 1) {
                r.x = fmaxf(r.x, 0.f); r.y = fmaxf(r.y, 0.f);
                r.z = fmaxf(r.z, 0.f); r.w = fmaxf(r.w, 0.f);
            }
            *(float4*)(crow + jj*4) = r;
        }
    }
}

// ---------------- bin encoder ----------------
__global__ void bin_enc_kernel(const float* __restrict__ bin,
                               const float* __restrict__ W1, const float* __restrict__ b1,
                               const float* __restrict__ W2, const float* __restrict__ b2,
                               float* __restrict__ bb)
{
    __shared__ float h1s[64];
    int b = blockIdx.x, j = threadIdx.x;
    float x0 = bin[b*2], x1 = bin[b*2+1];
    float h = fmaxf(fmaf(x0, W1[j*2], fmaf(x1, W1[j*2+1], b1[j])), 0.f);
    h1s[j] = h;
    __syncthreads();
    float acc = b2[j];
#pragma unroll 8
    for (int k = 0; k < 64; k++) acc = fmaf(h1s[k], W2[j*64 + k], acc);
    bb[b*64 + j] = acc;
}

// ---------------- concat: x = [p | bb | pos] ----------------
__global__ void concat_kernel(const float* __restrict__ p, const float* __restrict__ bb,
                              const float* __restrict__ pos, float* __restrict__ x)
{
    int idx = blockIdx.x * 128 + threadIdx.x;   // over 8192*64 float4s
    int r = idx >> 6, c4 = idx & 63;
    int b = r >> 8, s = r & 255;
    float4 v;
    if (c4 < 32)      v = ((const float4*)(p   + (size_t)r*128))[c4];
    else if (c4 < 48) v = ((const float4*)(bb  + (size_t)b*64))[c4-32];
    else              v = ((const float4*)(pos + (size_t)s*64))[c4-48];
    ((float4*)(x + (size_t)r*256))[c4] = v;
}

// ---------------- attention: one CTA per (b, head) ----------------
__global__ __launch_bounds__(128, 1) void attn_kernel(const float* __restrict__ qkv,
                                                      float* __restrict__ out)
{
    extern __shared__ float sm[];
    float* Ks = sm;              // [256][32]
    float* Vs = sm + 256*32;     // [256][32]
    int b = blockIdx.x >> 3, h = blockIdx.x & 7;
    int tid = threadIdx.x;
    const float scale = 0.17677669529663687f;

    for (int r = tid; r < 256; r += 128) {
        const float4* ksrc = (const float4*)(qkv + (size_t)(b*256 + r)*768 + 256 + h*32);
        const float4* vsrc = (const float4*)(qkv + (size_t)(b*256 + r)*768 + 512 + h*32);
        float4* kd = (float4*)(Ks + r*32);
        float4* vd = (float4*)(Vs + r*32);
#pragma unroll
        for (int i = 0; i < 8; i++) { kd[i] = ksrc[i]; vd[i] = vsrc[i]; }
    }
    float q0[32], q1[32], acc0[32], acc1[32];
    {
        const float4* q0f = (const float4*)(qkv + (size_t)(b*256 + tid)*768 + h*32);
        const float4* q1f = (const float4*)(qkv + (size_t)(b*256 + tid + 128)*768 + h*32);
#pragma unroll
        for (int i = 0; i < 8; i++) {
            float4 t0 = q0f[i], t1 = q1f[i];
            q0[i*4+0]=t0.x; q0[i*4+1]=t0.y; q0[i*4+2]=t0.z; q0[i*4+3]=t0.w;
            q1[i*4+0]=t1.x; q1[i*4+1]=t1.y; q1[i*4+2]=t1.z; q1[i*4+3]=t1.w;
        }
    }
#pragma unroll
    for (int i = 0; i < 32; i++) { acc0[i] = 0.f; acc1[i] = 0.f; }
    __syncthreads();

    float l0 = 0.f, l1 = 0.f;
    for (int k = 0; k < 256; k++) {
        float s0 = 0.f, s1 = 0.f;
        const float4* kr = (const float4*)(Ks + k*32);
#pragma unroll
        for (int i4 = 0; i4 < 8; i4++) {
            float4 kv = kr[i4];
            s0 = fmaf(q0[i4*4+0], kv.x, s0); s0 = fmaf(q0[i4*4+1], kv.y, s0);
            s0 = fmaf(q0[i4*4+2], kv.z, s0); s0 = fmaf(q0[i4*4+3], kv.w, s0);
            s1 = fmaf(q1[i4*4+0], kv.x, s1); s1 = fmaf(q1[i4*4+1], kv.y, s1);
            s1 = fmaf(q1[i4*4+2], kv.z, s1); s1 = fmaf(q1[i4*4+3], kv.w, s1);
        }
        float p0 = __expf(s0 * scale), p1 = __expf(s1 * scale);
        l0 += p0; l1 += p1;
        const float4* vr = (const float4*)(Vs + k*32);
#pragma unroll
        for (int i4 = 0; i4 < 8; i4++) {
            float4 vv = vr[i4];
            acc0[i4*4+0] = fmaf(p0, vv.x, acc0[i4*4+0]);
            acc0[i4*4+1] = fmaf(p0, vv.y, acc0[i4*4+1]);
            acc0[i4*4+2] = fmaf(p0, vv.z, acc0[i4*4+2]);
            acc0[i4*4+3] = fmaf(p0, vv.w, acc0[i4*4+3]);
            acc1[i4*4+0] = fmaf(p1, vv.x, acc1[i4*4+0]);
            acc1[i4*4+1] = fmaf(p1, vv.y, acc1[i4*4+1]);
            acc1[i4*4+2] = fmaf(p1, vv.z, acc1[i4*4+2]);
            acc1[i4*4+3] = fmaf(p1, vv.w, acc1[i4*4+3]);
        }
    }
    float inv0 = __fdividef(1.f, l0), inv1 = __fdividef(1.f, l1);
    float4* o0 = (float4*)(out + (size_t)(b*256 + tid)*256 + h*32);
    float4* o1 = (float4*)(out + (size_t)(b*256 + tid + 128)*256 + h*32);
#pragma unroll
    for (int i4 = 0; i4 < 8; i4++) {
        float4 r0, r1;
        r0.x = acc0[i4*4+0]*inv0; r0.y = acc0[i4*4+1]*inv0;
        r0.z = acc0[i4*4+2]*inv0; r0.w = acc0[i4*4+3]*inv0;
        r1.x = acc1[i4*4+0]*inv1; r1.y = acc1[i4*4+1]*inv1;
        r1.z = acc1[i4*4+2]*inv1; r1.w = acc1[i4*4+3]*inv1;
        o0[i4] = r0; o1[i4] = r1;
    }
}

// ---------------- residual + LayerNorm: out = LN(x + y) ----------------
__global__ void add_ln_kernel(const float* __restrict__ x, const float* __restrict__ y,
                              const float* __restrict__ g, const float* __restrict__ be,
                              float* __restrict__ out)
{
    int warp = threadIdx.x >> 5, lane = threadIdx.x & 31;
    size_t row = (size_t)blockIdx.x * 8 + warp;
    const float4* xr = (const float4*)(x + row*256);
    const float4* yr = (const float4*)(y + row*256);
    float4 a0 = xr[lane*2], a1 = xr[lane*2+1];
    float4 c0 = yr[lane*2], c1 = yr[lane*2+1];
    float v[8];
    v[0]=a0.x+c0.x; v[1]=a0.y+c0.y; v[2]=a0.z+c0.z; v[3]=a0.w+c0.w;
    v[4]=a1.x+c1.x; v[5]=a1.y+c1.y; v[6]=a1.z+c1.z; v[7]=a1.w+c1.w;
    float s = 0.f, s2 = 0.f;
#pragma unroll
    for (int i = 0; i < 8; i++) { s += v[i]; s2 = fmaf(v[i], v[i], s2); }
#pragma unroll
    for (int o = 16; o > 0; o >>= 1) {
        s  += __shfl_xor_sync(0xffffffffu, s,  o);
        s2 += __shfl_xor_sync(0xffffffffu, s2, o);
    }
    float mean = s * (1.f/256.f);
    float var  = s2 * (1.f/256.f) - mean*mean;
    float rstd = rsqrtf(var + 1e-5f);
    const float4* gf = (const float4*)(g + lane*8);
    const float4* bf = (const float4*)(be + lane*8);
    float4 g0 = gf[0], g1 = gf[1], b0 = bf[0], b1 = bf[1];
    float4 r0, r1;
    r0.x = (v[0]-mean)*rstd*g0.x + b0.x; r0.y = (v[1]-mean)*rstd*g0.y + b0.y;
    r0.z = (v[2]-mean)*rstd*g0.z + b0.z; r0.w = (v[3]-mean)*rstd*g0.w + b0.w;
    r1.x = (v[4]-mean)*rstd*g1.x + b1.x; r1.y = (v[5]-mean)*rstd*g1.y + b1.y;
    r1.z = (v[6]-mean)*rstd*g1.z + b1.z; r1.w = (v[7]-mean)*rstd*g1.w + b1.w;
    float4* orow = (float4*)(out + row*256);
    orow[lane*2]   = r0;
    orow[lane*2+1] = r1;
}

// ---------------- gather teacher-forced LSTM inputs ----------------
// xin row r = t*32+b : t==0 -> 0 ; else enc[b, target[b,t-1]]
__global__ void gather_kernel(const float* __restrict__ enc, const int* __restrict__ target,
                              float* __restrict__ xin)
{
    int idx = blockIdx.x * 256 + threadIdx.x;   // over 8192*64 float4s
    int r = idx >> 6, c4 = idx & 63;
    int t = r >> 5, b = r & 31;
    float4 val = make_float4(0.f, 0.f, 0.f, 0.f);
    if (t > 0) {
        int tgt = target[b*256 + t - 1];
        val = ((const float4*)(enc + (size_t)(b*256 + tgt)*256))[c4];
    }
    ((float4*)(xin + (size_t)r*256))[c4] = val;
}

// ---------------- LSTM: one CTA per batch, 1024 threads (one per gate col) --
__global__ __launch_bounds__(1024, 1) void lstm_kernel(
    const float* __restrict__ gin,   // [256*32][1024], row t*32+b (xin@Wih + bih + bhh)
    const float* __restrict__ Whh,   // [1024][256]
    float* __restrict__ hall)        // [256*32][256], row t*32+b
{
    __shared__ float h_s[256];
    __shared__ float g_s[1024];
    int b = blockIdx.x, tid = threadIdx.x;
    if (tid < 256) h_s[tid] = 0.f;
    float c = 0.f;
    const float4* wrow = (const float4*)(Whh + (size_t)tid * 256);
    __syncthreads();

    for (int t = 0; t < 256; t++) {
        float acc = gin[((size_t)(t*32 + b))*1024 + tid];
#pragma unroll 8
        for (int k4 = 0; k4 < 64; k4++) {
            float4 w  = __ldg(wrow + k4);
            float4 hh = *(const float4*)&h_s[k4*4];
            acc = fmaf(w.x, hh.x, acc); acc = fmaf(w.y, hh.y, acc);
            acc = fmaf(w.z, hh.z, acc); acc = fmaf(w.w, hh.w, acc);
        }
        g_s[tid] = acc;
        __syncthreads();
        if (tid < 256) {
            float gi = g_s[tid], gf = g_s[256+tid], gg = g_s[512+tid], go = g_s[768+tid];
            c = sigf(gf) * c + sigf(gi) * tanh_fast(gg);
            float h = sigf(go) * tanh_fast(c);
            h_s[tid] = h;
            hall[((size_t)(t*32 + b))*256 + tid] = h;
        }
        __syncthreads();
    }
}

// ---------------- logits: out[b][t][i] = sum_j v[j]*tanh(hp[t][b][j]+ep[b][i][j]) --
__global__ __launch_bounds__(256, 1) void logits_kernel(
    const float* __restrict__ hp, const float* __restrict__ ep,
    const float* __restrict__ v, float* __restrict__ out)
{
    extern __shared__ float sm[];
    float (*hps)[260] = (float(*)[260])sm;
    float (*eps)[260] = (float(*)[260])(sm + 32*260);
    float* vs = sm + 64*260;
    int b = blockIdx.z, tt = blockIdx.y*32, it = blockIdx.x*32;
    int tid = threadIdx.x;
    for (int idx = tid; idx < 32*64; idx += 256) {
        int r = idx >> 6, c4 = idx & 63;
        *(float4*)&hps[r][c4*4] = ((const float4*)(hp + ((size_t)(tt+r)*32 + b)*256))[c4];
        *(float4*)&eps[r][c4*4] = ((const float4*)(ep + ((size_t)b*256 + it + r)*256))[c4];
    }
    if (tid < 64) *(float4*)&vs[tid*4] = ((const float4*)v)[tid];
    __syncthreads();
    int ti = (tid >> 4) * 2, ii = (tid & 15) * 2;
    float s00=0.f, s01=0.f, s10=0.f, s11=0.f;
    for (int j = 0; j < 256; j++) {
        float vj = vs[j];
        float h0 = hps[ti][j], h1 = hps[ti+1][j];
        float e0 = eps[ii][j], e1 = eps[ii+1][j];
        s00 = fmaf(vj, tanh_fast(h0+e0), s00);
        s01 = fmaf(vj, tanh_fast(h0+e1), s01);
        s10 = fmaf(vj, tanh_fast(h1+e0), s10);
        s11 = fmaf(vj, tanh_fast(h1+e1), s11);
    }
    size_t base = ((size_t)b*256 + tt + ti)*256 + it + ii;
    out[base]       = s00; out[base+1]   = s01;
    out[base+256]   = s10; out[base+257] = s11;
}

// ---------------- host ----------------
extern "C" void kernel_launch(void* const* d_in, const int* in_sizes, int n_in,
                              void* d_out, int out_size)
{
    const float* parts    = (const float*)d_in[0];
    const float* bin_info = (const float*)d_in[1];
    const int*   target   = (const int*)  d_in[2];
    const float* pe_W1 = (const float*)d_in[3];
    const float* pe_b1 = (const float*)d_in[4];
    const float* pe_W2 = (const float*)d_in[5];
    const float* pe_b2 = (const float*)d_in[6];
    const float* be_W1 = (const float*)d_in[7];
    const float* be_b1 = (const float*)d_in[8];
    const float* be_W2 = (const float*)d_in[9];
    const float* be_b2 = (const float*)d_in[10];
    const float* pos_emb = (const float*)d_in[11];
    const float* tr_Wqkv = (const float*)d_in[12];
    const float* tr_bqkv = (const float*)d_in[13];
    const float* tr_Wo   = (const float*)d_in[14];
    const float* tr_bo   = (const float*)d_in[15];
    const float* tr_ln1_g = (const float*)d_in[16];
    const float* tr_ln1_b = (const float*)d_in[17];
    const float* tr_ff_W1 = (const float*)d_in[18];
    const float* tr_ff_b1 = (const float*)d_in[19];
    const float* tr_ff_W2 = (const float*)d_in[20];
    const float* tr_ff_b2 = (const float*)d_in[21];
    const float* tr_ln2_g = (const float*)d_in[22];
    const float* tr_ln2_b = (const float*)d_in[23];
    const float* lstm_Wih = (const float*)d_in[24];
    const float* lstm_Whh = (const float*)d_in[25];
    const float* lstm_bih = (const float*)d_in[26];
    const float* lstm_bhh = (const float*)d_in[27];
    const float* ptr_W = (const float*)d_in[28];
    const float* ptr_b = (const float*)d_in[29];
    const float* ptr_v = (const float*)d_in[30];
    float* out = (float*)d_out;

    float *x_, *qkv_, *att_, *ff_, *tmp_, *bb_, *ep_, *xin_, *gin_, *hall_, *hp_;
    cudaGetSymbolAddress((void**)&x_,   g_x);
    cudaGetSymbolAddress((void**)&qkv_, g_qkv);
    cudaGetSymbolAddress((void**)&att_, g_att);
    cudaGetSymbolAddress((void**)&ff_,  g_ff);
    cudaGetSymbolAddress((void**)&tmp_, g_tmp);
    cudaGetSymbolAddress((void**)&bb_,  g_bb);
    cudaGetSymbolAddress((void**)&ep_,  g_eproj);
    cudaGetSymbolAddress((void**)&xin_, g_xin);
    cudaGetSymbolAddress((void**)&gin_, g_gin);
    cudaGetSymbolAddress((void**)&hall_,g_hall);
    cudaGetSymbolAddress((void**)&hp_,  g_hp);

    cudaFuncSetAttribute(attn_kernel,   cudaFuncAttributeMaxDynamicSharedMemorySize, 65536);
    cudaFuncSetAttribute(logits_kernel, cudaFuncAttributeMaxDynamicSharedMemorySize, 69632);

    // encoders
    bin_enc_kernel<<<32, 64>>>(bin_info, be_W1, be_b1, be_W2, be_b2, bb_);
    sgemm_tn<1><<<dim3(1,64), 256>>>(parts, pe_W1, pe_b1, nullptr, att_, ROWS_, 128, 16);
    sgemm_tn<0><<<dim3(1,64), 256>>>(att_,  pe_W2, pe_b2, nullptr, tmp_, ROWS_, 128, 128);
    concat_kernel<<<4096, 128>>>(tmp_, bb_, pos_emb, x_);

    // transformer layers
    for (int l = 0; l < 3; l++) {
        sgemm_tn<0><<<dim3(6,64), 256>>>(x_, tr_Wqkv + (size_t)l*768*256,
                                         tr_bqkv + l*768, nullptr, qkv_, ROWS_, 768, 256);
        attn_kernel<<<256, 128, 65536>>>(qkv_, att_);
        sgemm_tn<0><<<dim3(2,64), 256>>>(att_, tr_Wo + (size_t)l*256*256,
                                         tr_bo + l*256, nullptr, tmp_, ROWS_, 256, 256);
        add_ln_kernel<<<1024, 256>>>(x_, tmp_, tr_ln1_g + l*256, tr_ln1_b + l*256, x_);
        sgemm_tn<1><<<dim3(4,64), 256>>>(x_, tr_ff_W1 + (size_t)l*512*256,
                                         tr_ff_b1 + l*512, nullptr, ff_, ROWS_, 512, 256);
        sgemm_tn<0><<<dim3(2,64), 256>>>(ff_, tr_ff_W2 + (size_t)l*256*512,
                                         tr_ff_b2 + l*256, nullptr, tmp_, ROWS_, 256, 512);
        add_ln_kernel<<<1024, 256>>>(x_, tmp_, tr_ln2_g + l*256, tr_ln2_b + l*256, x_);
    }

    // pointer decode
    sgemm_tn<0><<<dim3(2,64), 256>>>(x_, ptr_W, ptr_b, nullptr, ep_, ROWS_, 256, 256);
    gather_kernel<<<2048, 256>>>(x_, target, xin_);
    sgemm_tn<0><<<dim3(8,64), 256>>>(xin_, lstm_Wih, lstm_bih, lstm_bhh, gin_, ROWS_, 1024, 256);
    lstm_kernel<<<32, 1024>>>(gin_, lstm_Whh, hall_);
    sgemm_tn<0><<<dim3(2,64), 256>>>(hall_, ptr_W, ptr_b, nullptr, hp_, ROWS_, 256, 256);
    logits_kernel<<<dim3(8,8,32), 256, 69632>>>(hp_, ep_, ptr_v, out);
}

// round 4
// speedup vs baseline: 2.7647x; 2.7647x over previous
#include <cuda_runtime.h>
#include <cuda_bf16.h>
#include <cstdint>

#define ROWS_ 8192
#define LSTM_PARTS 8

// ---------------- device scratch ----------------
__device__ float g_x    [ROWS_*256];
__device__ float g_qkv  [ROWS_*768];
__device__ float g_att  [ROWS_*256];
__device__ float g_ff   [ROWS_*512];
__device__ float g_tmp  [ROWS_*256];
__device__ float g_bb   [32*64];
__device__ float g_eproj[ROWS_*256];
__device__ float g_xin  [ROWS_*256];
__device__ float g_gin  [ROWS_*1024];
__device__ float g_hall [ROWS_*256];
__device__ float g_hp   [ROWS_*256];
__device__ float g_hbuf [2*32*256];
__device__ int   g_cnt  [32*256];

__device__ __forceinline__ float sigf(float x) {
    return __fdividef(1.f, 1.f + __expf(-x));
}
__device__ __forceinline__ float tanh_acc(float x) {
    float xx = fminf(fmaxf(x, -15.f), 15.f);
    float e  = __expf(2.f * xx);
    return __fdividef(e - 1.f, e + 1.f);
}
__device__ __forceinline__ float tanh_approx(float x) {
    float y;
    asm("tanh.approx.f32 %0, %1;" : "=f"(y) : "f"(x));
    return y;
}

// ---------------- SGEMM: C[M,N] = A[M,K] @ W[N,K]^T + bias (+bias2), opt ReLU
template<int ACT>
__global__ __launch_bounds__(256, 2) void sgemm_tn(
    const float* __restrict__ A, const float* __restrict__ W,
    const float* __restrict__ bias, const float* __restrict__ bias2,
    float* __restrict__ C, int M, int N, int K)
{
    __shared__ float As[8][128];
    __shared__ float Ws[8][128];
    int tid = threadIdx.x;
    int m0 = blockIdx.y * 128;
    int n0 = blockIdx.x * 128;
    int lr = tid >> 1;
    int lk = (tid & 1) * 4;
    const float* Aptr = A + (size_t)(m0 + lr) * K + lk;
    const float* Wptr = W + (size_t)(n0 + lr) * K + lk;
    int tx = tid & 15, ty = tid >> 4;

    float acc[8][8];
#pragma unroll
    for (int i = 0; i < 8; i++)
#pragma unroll
        for (int j = 0; j < 8; j++) acc[i][j] = 0.f;

    float4 a4 = *(const float4*)Aptr;
    float4 w4 = *(const float4*)Wptr;

    for (int kt = 0; kt < K; kt += 8) {
        As[lk+0][lr] = a4.x; As[lk+1][lr] = a4.y; As[lk+2][lr] = a4.z; As[lk+3][lr] = a4.w;
        Ws[lk+0][lr] = w4.x; Ws[lk+1][lr] = w4.y; Ws[lk+2][lr] = w4.z; Ws[lk+3][lr] = w4.w;
        __syncthreads();
        if (kt + 8 < K) {
            a4 = *(const float4*)(Aptr + kt + 8);
            w4 = *(const float4*)(Wptr + kt + 8);
        }
#pragma unroll
        for (int kk = 0; kk < 8; kk++) {
            float4 a0 = *(const float4*)&As[kk][ty*8];
            float4 a1 = *(const float4*)&As[kk][ty*8+4];
            float4 b0 = *(const float4*)&Ws[kk][tx*8];
            float4 b1 = *(const float4*)&Ws[kk][tx*8+4];
            float a[8] = {a0.x,a0.y,a0.z,a0.w,a1.x,a1.y,a1.z,a1.w};
            float b[8] = {b0.x,b0.y,b0.z,b0.w,b1.x,b1.y,b1.z,b1.w};
#pragma unroll
            for (int i = 0; i < 8; i++)
#pragma unroll
                for (int j = 0; j < 8; j++) acc[i][j] = fmaf(a[i], b[j], acc[i][j]);
        }
        __syncthreads();
    }

#pragma unroll
    for (int i = 0; i < 8; i++) {
        size_t m = (size_t)(m0 + ty*8 + i);
        float* crow = C + m * N + n0 + tx*8;
#pragma unroll
        for (int jj = 0; jj < 2; jj++) {
            int nb = n0 + tx*8 + jj*4;
            float4 bv = *(const float4*)(bias + nb);
            if (bias2) {
                float4 b2 = *(const float4*)(bias2 + nb);
                bv.x += b2.x; bv.y += b2.y; bv.z += b2.z; bv.w += b2.w;
            }
            float4 r;
            r.x = acc[i][jj*4+0] + bv.x;
            r.y = acc[i][jj*4+1] + bv.y;
            r.z = acc[i][jj*4+2] + bv.z;
            r.w = acc[i][jj*4+3] + bv.w;
            if (ACT == 1) {
                r.x = fmaxf(r.x, 0.f); r.y = fmaxf(r.y, 0.f);
                r.z = fmaxf(r.z, 0.f); r.w = fmaxf(r.w, 0.f);
            }
            *(float4*)(crow + jj*4) = r;
        }
    }
}

// ---------------- bin encoder ----------------
__global__ void bin_enc_kernel(const float* __restrict__ bin,
                               const float* __restrict__ W1, const float* __restrict__ b1,
                               const float* __restrict__ W2, const float* __restrict__ b2,
                               float* __restrict__ bb)
{
    __shared__ float h1s[64];
    int b = blockIdx.x, j = threadIdx.x;
    float x0 = bin[b*2], x1 = bin[b*2+1];
    float h = fmaxf(fmaf(x0, W1[j*2], fmaf(x1, W1[j*2+1], b1[j])), 0.f);
    h1s[j] = h;
    __syncthreads();
    float acc = b2[j];
#pragma unroll 8
    for (int k = 0; k < 64; k++) acc = fmaf(h1s[k], W2[j*64 + k], acc);
    bb[b*64 + j] = acc;
}

// ---------------- concat: x = [p | bb | pos] ----------------
__global__ void concat_kernel(const float* __restrict__ p, const float* __restrict__ bb,
                              const float* __restrict__ pos, float* __restrict__ x)
{
    int idx = blockIdx.x * 128 + threadIdx.x;
    int r = idx >> 6, c4 = idx & 63;
    int b = r >> 8, s = r & 255;
    float4 v;
    if (c4 < 32)      v = ((const float4*)(p   + (size_t)r*128))[c4];
    else if (c4 < 48) v = ((const float4*)(bb  + (size_t)b*64))[c4-32];
    else              v = ((const float4*)(pos + (size_t)s*64))[c4-48];
    ((float4*)(x + (size_t)r*256))[c4] = v;
}

// ---------------- attention: one CTA per (b, head) ----------------
__global__ __launch_bounds__(128, 1) void attn_kernel(const float* __restrict__ qkv,
                                                      float* __restrict__ out)
{
    extern __shared__ float sm[];
    float* Ks = sm;
    float* Vs = sm + 256*32;
    int b = blockIdx.x >> 3, h = blockIdx.x & 7;
    int tid = threadIdx.x;
    const float scale = 0.17677669529663687f;

    for (int r = tid; r < 256; r += 128) {
        const float4* ksrc = (const float4*)(qkv + (size_t)(b*256 + r)*768 + 256 + h*32);
        const float4* vsrc = (const float4*)(qkv + (size_t)(b*256 + r)*768 + 512 + h*32);
        float4* kd = (float4*)(Ks + r*32);
        float4* vd = (float4*)(Vs + r*32);
#pragma unroll
        for (int i = 0; i < 8; i++) { kd[i] = ksrc[i]; vd[i] = vsrc[i]; }
    }
    float q0[32], q1[32], acc0[32], acc1[32];
    {
        const float4* q0f = (const float4*)(qkv + (size_t)(b*256 + tid)*768 + h*32);
        const float4* q1f = (const float4*)(qkv + (size_t)(b*256 + tid + 128)*768 + h*32);
#pragma unroll
        for (int i = 0; i < 8; i++) {
            float4 t0 = q0f[i], t1 = q1f[i];
            q0[i*4+0]=t0.x; q0[i*4+1]=t0.y; q0[i*4+2]=t0.z; q0[i*4+3]=t0.w;
            q1[i*4+0]=t1.x; q1[i*4+1]=t1.y; q1[i*4+2]=t1.z; q1[i*4+3]=t1.w;
        }
    }
#pragma unroll
    for (int i = 0; i < 32; i++) { acc0[i] = 0.f; acc1[i] = 0.f; }
    __syncthreads();

    float l0 = 0.f, l1 = 0.f;
    for (int k = 0; k < 256; k++) {
        float s0 = 0.f, s1 = 0.f;
        const float4* kr = (const float4*)(Ks + k*32);
#pragma unroll
        for (int i4 = 0; i4 < 8; i4++) {
            float4 kv = kr[i4];
            s0 = fmaf(q0[i4*4+0], kv.x, s0); s0 = fmaf(q0[i4*4+1], kv.y, s0);
            s0 = fmaf(q0[i4*4+2], kv.z, s0); s0 = fmaf(q0[i4*4+3], kv.w, s0);
            s1 = fmaf(q1[i4*4+0], kv.x, s1); s1 = fmaf(q1[i4*4+1], kv.y, s1);
            s1 = fmaf(q1[i4*4+2], kv.z, s1); s1 = fmaf(q1[i4*4+3], kv.w, s1);
        }
        float p0 = __expf(s0 * scale), p1 = __expf(s1 * scale);
        l0 += p0; l1 += p1;
        const float4* vr = (const float4*)(Vs + k*32);
#pragma unroll
        for (int i4 = 0; i4 < 8; i4++) {
            float4 vv = vr[i4];
            acc0[i4*4+0] = fmaf(p0, vv.x, acc0[i4*4+0]);
            acc0[i4*4+1] = fmaf(p0, vv.y, acc0[i4*4+1]);
            acc0[i4*4+2] = fmaf(p0, vv.z, acc0[i4*4+2]);
            acc0[i4*4+3] = fmaf(p0, vv.w, acc0[i4*4+3]);
            acc1[i4*4+0] = fmaf(p1, vv.x, acc1[i4*4+0]);
            acc1[i4*4+1] = fmaf(p1, vv.y, acc1[i4*4+1]);
            acc1[i4*4+2] = fmaf(p1, vv.z, acc1[i4*4+2]);
            acc1[i4*4+3] = fmaf(p1, vv.w, acc1[i4*4+3]);
        }
    }
    float inv0 = __fdividef(1.f, l0), inv1 = __fdividef(1.f, l1);
    float4* o0 = (float4*)(out + (size_t)(b*256 + tid)*256 + h*32);
    float4* o1 = (float4*)(out + (size_t)(b*256 + tid + 128)*256 + h*32);
#pragma unroll
    for (int i4 = 0; i4 < 8; i4++) {
        float4 r0, r1;
        r0.x = acc0[i4*4+0]*inv0; r0.y = acc0[i4*4+1]*inv0;
        r0.z = acc0[i4*4+2]*inv0; r0.w = acc0[i4*4+3]*inv0;
        r1.x = acc1[i4*4+0]*inv1; r1.y = acc1[i4*4+1]*inv1;
        r1.z = acc1[i4*4+2]*inv1; r1.w = acc1[i4*4+3]*inv1;
        o0[i4] = r0; o1[i4] = r1;
    }
}

// ---------------- residual + LayerNorm ----------------
__global__ void add_ln_kernel(const float* __restrict__ x, const float* __restrict__ y,
                              const float* __restrict__ g, const float* __restrict__ be,
                              float* __restrict__ out)
{
    int warp = threadIdx.x >> 5, lane = threadIdx.x & 31;
    size_t row = (size_t)blockIdx.x * 8 + warp;
    const float4* xr = (const float4*)(x + row*256);
    const float4* yr = (const float4*)(y + row*256);
    float4 a0 = xr[lane*2], a1 = xr[lane*2+1];
    float4 c0 = yr[lane*2], c1 = yr[lane*2+1];
    float v[8];
    v[0]=a0.x+c0.x; v[1]=a0.y+c0.y; v[2]=a0.z+c0.z; v[3]=a0.w+c0.w;
    v[4]=a1.x+c1.x; v[5]=a1.y+c1.y; v[6]=a1.z+c1.z; v[7]=a1.w+c1.w;
    float s = 0.f, s2 = 0.f;
#pragma unroll
    for (int i = 0; i < 8; i++) { s += v[i]; s2 = fmaf(v[i], v[i], s2); }
#pragma unroll
    for (int o = 16; o > 0; o >>= 1) {
        s  += __shfl_xor_sync(0xffffffffu, s,  o);
        s2 += __shfl_xor_sync(0xffffffffu, s2, o);
    }
    float mean = s * (1.f/256.f);
    float var  = s2 * (1.f/256.f) - mean*mean;
    float rstd = rsqrtf(var + 1e-5f);
    const float4* gf = (const float4*)(g + lane*8);
    const float4* bf = (const float4*)(be + lane*8);
    float4 g0 = gf[0], g1 = gf[1], b0 = bf[0], b1 = bf[1];
    float4 r0, r1;
    r0.x = (v[0]-mean)*rstd*g0.x + b0.x; r0.y = (v[1]-mean)*rstd*g0.y + b0.y;
    r0.z = (v[2]-mean)*rstd*g0.z + b0.z; r0.w = (v[3]-mean)*rstd*g0.w + b0.w;
    r1.x = (v[4]-mean)*rstd*g1.x + b1.x; r1.y = (v[5]-mean)*rstd*g1.y + b1.y;
    r1.z = (v[6]-mean)*rstd*g1.z + b1.z; r1.w = (v[7]-mean)*rstd*g1.w + b1.w;
    float4* orow = (float4*)(out + row*256);
    orow[lane*2]   = r0;
    orow[lane*2+1] = r1;
}

// ---------------- gather teacher-forced LSTM inputs ----------------
__global__ void gather_kernel(const float* __restrict__ enc, const int* __restrict__ target,
                              float* __restrict__ xin)
{
    int idx = blockIdx.x * 256 + threadIdx.x;
    int r = idx >> 6, c4 = idx & 63;
    int t = r >> 5, b = r & 31;
    float4 val = make_float4(0.f, 0.f, 0.f, 0.f);
    if (t > 0) {
        int tgt = target[b*256 + t - 1];
        val = ((const float4*)(enc + (size_t)(b*256 + tgt)*256))[c4];
    }
    ((float4*)(xin + (size_t)r*256))[c4] = val;
}

// ---------------- zero the lstm step counters (every replay) ----------------
__global__ void lstm_init_kernel(int* __restrict__ cnt)
{
    int idx = blockIdx.x * 256 + threadIdx.x;
    if (idx < 32*256) cnt[idx] = 0;
}

// ---------------- LSTM: 256 CTAs = 32 batches x 8 parts, Whh in registers ----
// CTA (b,part) owns h-columns [part*32, part*32+32) -> 128 gate columns.
// Thread: p = tid>>1 (gate*32+jj), half = tid&1 -> 128 Whh weights in regs.
// h exchanged via global ping-pong buffer + per-(batch,step) release counter.
__global__ __launch_bounds__(256, 1) void lstm_kernel(
    const float* __restrict__ gin,   // [256*32][1024] row t*32+b
    const float* __restrict__ Whh,   // [1024][256]
    float* __restrict__ hall,        // [256*32][256]
    float* __restrict__ hbuf,        // [2][32][256]
    int* __restrict__ cnt)           // [32][256]
{
    __shared__ float h_s[256];
    __shared__ float g_s[128];
    int b = blockIdx.x >> 3, part = blockIdx.x & 7;
    int tid = threadIdx.x;
    int p = tid >> 1, half = tid & 1;
    int gate = p >> 5, jj = p & 31;
    int col = gate * 256 + part * 32 + jj;

    float w[128];
    {
        const float4* wsrc = (const float4*)(Whh + (size_t)col * 256 + half * 128);
#pragma unroll
        for (int i = 0; i < 32; i++) {
            float4 v = wsrc[i];
            w[i*4+0]=v.x; w[i*4+1]=v.y; w[i*4+2]=v.z; w[i*4+3]=v.w;
        }
    }
    float c = 0.f;
    if (tid < 256) h_s[tid] = 0.f;
    __syncthreads();

    volatile int* vcnt = cnt + b * 256;
    for (int t = 0; t < 256; t++) {
        if (t > 0) {
            if (tid == 0) { while (vcnt[t-1] < LSTM_PARTS) { } }
            __syncthreads();
            const float4* hsrc = (const float4*)(hbuf + ((size_t)((t & 1) * 32 + b)) * 256);
            if (tid < 64) *(float4*)&h_s[tid*4] = __ldcg(hsrc + tid);
            __syncthreads();
        }
        float a0 = 0.f, a1 = 0.f, a2 = 0.f, a3 = 0.f;
        const float4* h4 = (const float4*)&h_s[half * 128];
#pragma unroll
        for (int k4 = 0; k4 < 32; k4 += 4) {
            float4 h0 = h4[k4], h1 = h4[k4+1], h2 = h4[k4+2], h3 = h4[k4+3];
            a0 = fmaf(w[k4*4+0],  h0.x, a0); a0 = fmaf(w[k4*4+1],  h0.y, a0);
            a0 = fmaf(w[k4*4+2],  h0.z, a0); a0 = fmaf(w[k4*4+3],  h0.w, a0);
            a1 = fmaf(w[k4*4+4],  h1.x, a1); a1 = fmaf(w[k4*4+5],  h1.y, a1);
            a1 = fmaf(w[k4*4+6],  h1.z, a1); a1 = fmaf(w[k4*4+7],  h1.w, a1);
            a2 = fmaf(w[k4*4+8],  h2.x, a2); a2 = fmaf(w[k4*4+9],  h2.y, a2);
            a2 = fmaf(w[k4*4+10], h2.z, a2); a2 = fmaf(w[k4*4+11], h2.w, a2);
            a3 = fmaf(w[k4*4+12], h3.x, a3); a3 = fmaf(w[k4*4+13], h3.y, a3);
            a3 = fmaf(w[k4*4+14], h3.z, a3); a3 = fmaf(w[k4*4+15], h3.w, a3);
        }
        float acc = (a0 + a1) + (a2 + a3);
        acc += __shfl_xor_sync(0xffffffffu, acc, 1);
        if (half == 0) {
            float gv = __ldcg(gin + ((size_t)(t*32 + b))*1024 + col);
            g_s[p] = acc + gv;
        }
        __syncthreads();
        if (tid < 32) {
            float gi = g_s[tid], gf = g_s[32+tid], gg = g_s[64+tid], go = g_s[96+tid];
            c = sigf(gf) * c + sigf(gi) * tanh_acc(gg);
            float h = sigf(go) * tanh_acc(c);
            int colh = part*32 + tid;
            hbuf[((size_t)(((t+1) & 1) * 32 + b))*256 + colh] = h;
            hall[((size_t)(t*32 + b))*256 + colh] = h;
        }
        __threadfence();
        __syncthreads();
        if (tid == 0) atomicAdd(cnt + b*256 + t, 1);
    }
}

// ---------------- logits: out[b][t][i] = sum_j v[j]*tanh(hp[t][b][j]+ep[b][i][j]) --
__global__ __launch_bounds__(256, 1) void logits_kernel(
    const float* __restrict__ hp, const float* __restrict__ ep,
    const float* __restrict__ v, float* __restrict__ out)
{
    extern __shared__ float sm[];
    float (*hps)[260] = (float(*)[260])sm;
    float (*eps)[260] = (float(*)[260])(sm + 32*260);
    float* vs = sm + 64*260;
    int b = blockIdx.z, tt = blockIdx.y*32, it = blockIdx.x*32;
    int tid = threadIdx.x;
    for (int idx = tid; idx < 32*64; idx += 256) {
        int r = idx >> 6, c4 = idx & 63;
        *(float4*)&hps[r][c4*4] = ((const float4*)(hp + ((size_t)(tt+r)*32 + b)*256))[c4];
        *(float4*)&eps[r][c4*4] = ((const float4*)(ep + ((size_t)b*256 + it + r)*256))[c4];
    }
    if (tid < 64) *(float4*)&vs[tid*4] = ((const float4*)v)[tid];
    __syncthreads();
    int ti = (tid >> 4) * 2, ii = (tid & 15) * 2;
    float s00=0.f, s01=0.f, s10=0.f, s11=0.f;
    for (int j = 0; j < 256; j++) {
        float vj = vs[j];
        float h0 = hps[ti][j], h1 = hps[ti+1][j];
        float e0 = eps[ii][j], e1 = eps[ii+1][j];
        s00 = fmaf(vj, tanh_approx(h0+e0), s00);
        s01 = fmaf(vj, tanh_approx(h0+e1), s01);
        s10 = fmaf(vj, tanh_approx(h1+e0), s10);
        s11 = fmaf(vj, tanh_approx(h1+e1), s11);
    }
    size_t base = ((size_t)b*256 + tt + ti)*256 + it + ii;
    out[base]       = s00; out[base+1]   = s01;
    out[base+256]   = s10; out[base+257] = s11;
}

// ---------------- host ----------------
extern "C" void kernel_launch(void* const* d_in, const int* in_sizes, int n_in,
                              void* d_out, int out_size)
{
    const float* parts    = (const float*)d_in[0];
    const float* bin_info = (const float*)d_in[1];
    const int*   target   = (const int*)  d_in[2];
    const float* pe_W1 = (const float*)d_in[3];
    const float* pe_b1 = (const float*)d_in[4];
    const float* pe_W2 = (const float*)d_in[5];
    const float* pe_b2 = (const float*)d_in[6];
    const float* be_W1 = (const float*)d_in[7];
    const float* be_b1 = (const float*)d_in[8];
    const float* be_W2 = (const float*)d_in[9];
    const float* be_b2 = (const float*)d_in[10];
    const float* pos_emb = (const float*)d_in[11];
    const float* tr_Wqkv = (const float*)d_in[12];
    const float* tr_bqkv = (const float*)d_in[13];
    const float* tr_Wo   = (const float*)d_in[14];
    const float* tr_bo   = (const float*)d_in[15];
    const float* tr_ln1_g = (const float*)d_in[16];
    const float* tr_ln1_b = (const float*)d_in[17];
    const float* tr_ff_W1 = (const float*)d_in[18];
    const float* tr_ff_b1 = (const float*)d_in[19];
    const float* tr_ff_W2 = (const float*)d_in[20];
    const float* tr_ff_b2 = (const float*)d_in[21];
    const float* tr_ln2_g = (const float*)d_in[22];
    const float* tr_ln2_b = (const float*)d_in[23];
    const float* lstm_Wih = (const float*)d_in[24];
    const float* lstm_Whh = (const float*)d_in[25];
    const float* lstm_bih = (const float*)d_in[26];
    const float* lstm_bhh = (const float*)d_in[27];
    const float* ptr_W = (const float*)d_in[28];
    const float* ptr_b = (const float*)d_in[29];
    const float* ptr_v = (const float*)d_in[30];
    float* out = (float*)d_out;

    float *x_, *qkv_, *att_, *ff_, *tmp_, *bb_, *ep_, *xin_, *gin_, *hall_, *hp_, *hbuf_;
    int* cnt_;
    cudaGetSymbolAddress((void**)&x_,    g_x);
    cudaGetSymbolAddress((void**)&qkv_,  g_qkv);
    cudaGetSymbolAddress((void**)&att_,  g_att);
    cudaGetSymbolAddress((void**)&ff_,   g_ff);
    cudaGetSymbolAddress((void**)&tmp_,  g_tmp);
    cudaGetSymbolAddress((void**)&bb_,   g_bb);
    cudaGetSymbolAddress((void**)&ep_,   g_eproj);
    cudaGetSymbolAddress((void**)&xin_,  g_xin);
    cudaGetSymbolAddress((void**)&gin_,  g_gin);
    cudaGetSymbolAddress((void**)&hall_, g_hall);
    cudaGetSymbolAddress((void**)&hp_,   g_hp);
    cudaGetSymbolAddress((void**)&hbuf_, g_hbuf);
    cudaGetSymbolAddress((void**)&cnt_,  g_cnt);

    cudaFuncSetAttribute(attn_kernel,   cudaFuncAttributeMaxDynamicSharedMemorySize, 65536);
    cudaFuncSetAttribute(logits_kernel, cudaFuncAttributeMaxDynamicSharedMemorySize, 69632);

    // encoders
    bin_enc_kernel<<<32, 64>>>(bin_info, be_W1, be_b1, be_W2, be_b2, bb_);
    sgemm_tn<1><<<dim3(1,64), 256>>>(parts, pe_W1, pe_b1, nullptr, att_, ROWS_, 128, 16);
    sgemm_tn<0><<<dim3(1,64), 256>>>(att_,  pe_W2, pe_b2, nullptr, tmp_, ROWS_, 128, 128);
    concat_kernel<<<4096, 128>>>(tmp_, bb_, pos_emb, x_);

    // transformer layers
    for (int l = 0; l < 3; l++) {
        sgemm_tn<0><<<dim3(6,64), 256>>>(x_, tr_Wqkv + (size_t)l*768*256,
                                         tr_bqkv + l*768, nullptr, qkv_, ROWS_, 768, 256);
        attn_kernel<<<256, 128, 65536>>>(qkv_, att_);
        sgemm_tn<0><<<dim3(2,64), 256>>>(att_, tr_Wo + (size_t)l*256*256,
                                         tr_bo + l*256, nullptr, tmp_, ROWS_, 256, 256);
        add_ln_kernel<<<1024, 256>>>(x_, tmp_, tr_ln1_g + l*256, tr_ln1_b + l*256, x_);
        sgemm_tn<1><<<dim3(4,64), 256>>>(x_, tr_ff_W1 + (size_t)l*512*256,
                                         tr_ff_b1 + l*512, nullptr, ff_, ROWS_, 512, 256);
        sgemm_tn<0><<<dim3(2,64), 256>>>(ff_, tr_ff_W2 + (size_t)l*256*512,
                                         tr_ff_b2 + l*256, nullptr, tmp_, ROWS_, 256, 512);
        add_ln_kernel<<<1024, 256>>>(x_, tmp_, tr_ln2_g + l*256, tr_ln2_b + l*256, x_);
    }

    // pointer decode
    sgemm_tn<0><<<dim3(2,64), 256>>>(x_, ptr_W, ptr_b, nullptr, ep_, ROWS_, 256, 256);
    gather_kernel<<<2048, 256>>>(x_, target, xin_);
    sgemm_tn<0><<<dim3(8,64), 256>>>(xin_, lstm_Wih, lstm_bih, lstm_bhh, gin_, ROWS_, 1024, 256);
    lstm_init_kernel<<<32, 256>>>(cnt_);
    lstm_kernel<<<256, 256>>>(gin_, lstm_Whh, hall_, hbuf_, cnt_);
    sgemm_tn<0><<<dim3(2,64), 256>>>(hall_, ptr_W, ptr_b, nullptr, hp_, ROWS_, 256, 256);
    logits_kernel<<<dim3(8,8,32), 256, 69632>>>(hp_, ep_, ptr_v, out);
}

// round 5
// speedup vs baseline: 3.9330x; 1.4226x over previous
#include <cuda_runtime.h>
#include <cuda_bf16.h>
#include <cstdint>

#define ROWS_ 8192
#define LSTM_PARTS 8

// weight-split buffer offsets (floats)
#define OFF_PEW1 0
#define OFF_PEW2 2048
#define OFF_WQKV 18432
#define OFF_WO   608256
#define OFF_FFW1 804864
#define OFF_FFW2 1198080
#define OFF_WIH  1591296
#define OFF_PTRW 1853440
#define W_TOTAL  1918976

// ---------------- device scratch ----------------
__device__ float g_x    [ROWS_*256];
__device__ float g_qkv  [ROWS_*768];
__device__ float g_ff   [ROWS_*512];   // unused plain (kept for safety)
__device__ float g_tmp  [ROWS_*256];
__device__ float g_bb   [32*64];
__device__ float g_eproj[ROWS_*256];
__device__ float g_gin  [ROWS_*1024];
__device__ float g_hp   [ROWS_*256];
__device__ float g_hbuf [2*32*256];
__device__ int   g_cnt  [32*256];
// split pairs
__device__ float g_whi[W_TOTAL], g_wlo[W_TOTAL];
__device__ float g_phi[ROWS_*16],  g_plo[ROWS_*16];
__device__ float g_xhi[ROWS_*256], g_xlo[ROWS_*256];
__device__ float g_athi[ROWS_*256], g_atlo[ROWS_*256];
__device__ float g_ffhi[ROWS_*512], g_fflo[ROWS_*512];
__device__ float g_xihi[ROWS_*256], g_xilo[ROWS_*256];
__device__ float g_hahi[ROWS_*256], g_halo[ROWS_*256];

__device__ __forceinline__ float sigf(float x) {
    return __fdividef(1.f, 1.f + __expf(-x));
}
__device__ __forceinline__ float tanh_acc(float x) {
    float xx = fminf(fmaxf(x, -15.f), 15.f);
    float e  = __expf(2.f * xx);
    return __fdividef(e - 1.f, e + 1.f);
}
__device__ __forceinline__ float tanh_approx(float x) {
    float y;
    asm("tanh.approx.f32 %0, %1;" : "=f"(y) : "f"(x));
    return y;
}
__device__ __forceinline__ void split2(float x, float& hi, float& lo) {
    hi = __uint_as_float(__float_as_uint(x) & 0xFFFFE000u);
    lo = x - hi;
}

// ---------------- generic splitter ----------------
__global__ void split_kernel(const float* __restrict__ src, float* __restrict__ hi,
                             float* __restrict__ lo, int n)
{
    int i = blockIdx.x * 256 + threadIdx.x;
    if (i < n) { float h, l; split2(src[i], h, l); hi[i] = h; lo[i] = l; }
}

// ---------------- tf32 3x-split tensor-core GEMM ----------------
// C[M,N] = A[M,K] @ W[N,K]^T + bias (+bias2). M%128==0, N%128==0, K%16==0.
// A and W supplied pre-split (hi/lo). SPLIT_OUT: writes Ch/Cl instead of C.
__device__ __forceinline__ void mma_tf32(float* c, const float* a, float b0, float b1) {
    asm volatile(
        "mma.sync.aligned.m16n8k8.row.col.f32.tf32.tf32.f32 "
        "{%0,%1,%2,%3}, {%4,%5,%6,%7}, {%8,%9}, {%0,%1,%2,%3};\n"
        : "+f"(c[0]), "+f"(c[1]), "+f"(c[2]), "+f"(c[3])
        : "r"(__float_as_uint(a[0])), "r"(__float_as_uint(a[1])),
          "r"(__float_as_uint(a[2])), "r"(__float_as_uint(a[3])),
          "r"(__float_as_uint(b0)),   "r"(__float_as_uint(b1)));
}

template<int ACT, int SPLIT_OUT>
__global__ __launch_bounds__(256, 1) void tgemm(
    const float* __restrict__ Ah, const float* __restrict__ Al,
    const float* __restrict__ Wh, const float* __restrict__ Wl,
    const float* __restrict__ bias, const float* __restrict__ bias2,
    float* __restrict__ C, float* __restrict__ Ch, float* __restrict__ Cl,
    int M, int N, int K)
{
    __shared__ float SAh[16][136], SAl[16][136], SBh[16][136], SBl[16][136];
    int tid = threadIdx.x;
    int m0 = blockIdx.y * 128, n0 = blockIdx.x * 128;
    int warp = tid >> 5, lane = tid & 31;
    int g = lane >> 2, tg = lane & 3;
    int moff = (warp >> 2) * 64, noff = (warp & 3) * 32;

    int lr = tid >> 1, lk4 = (tid & 1) * 4;
    const float* Ahp = Ah + (size_t)(m0 + lr) * K + lk4;
    const float* Alp = Al + (size_t)(m0 + lr) * K + lk4;
    const float* Whp = Wh + (size_t)(n0 + lr) * K + lk4;
    const float* Wlp = Wl + (size_t)(n0 + lr) * K + lk4;

    float c_[4][4][4];
#pragma unroll
    for (int i = 0; i < 4; i++)
#pragma unroll
        for (int j = 0; j < 4; j++)
#pragma unroll
            for (int r = 0; r < 4; r++) c_[i][j][r] = 0.f;

    float4 ah0 = *(const float4*)Ahp,       ah1 = *(const float4*)(Ahp + 8);
    float4 al0 = *(const float4*)Alp,       al1 = *(const float4*)(Alp + 8);
    float4 wh0 = *(const float4*)Whp,       wh1 = *(const float4*)(Whp + 8);
    float4 wl0 = *(const float4*)Wlp,       wl1 = *(const float4*)(Wlp + 8);

    for (int kt = 0; kt < K; kt += 16) {
        SAh[lk4+0][lr]=ah0.x; SAh[lk4+1][lr]=ah0.y; SAh[lk4+2][lr]=ah0.z; SAh[lk4+3][lr]=ah0.w;
        SAh[lk4+8][lr]=ah1.x; SAh[lk4+9][lr]=ah1.y; SAh[lk4+10][lr]=ah1.z; SAh[lk4+11][lr]=ah1.w;
        SAl[lk4+0][lr]=al0.x; SAl[lk4+1][lr]=al0.y; SAl[lk4+2][lr]=al0.z; SAl[lk4+3][lr]=al0.w;
        SAl[lk4+8][lr]=al1.x; SAl[lk4+9][lr]=al1.y; SAl[lk4+10][lr]=al1.z; SAl[lk4+11][lr]=al1.w;
        SBh[lk4+0][lr]=wh0.x; SBh[lk4+1][lr]=wh0.y; SBh[lk4+2][lr]=wh0.z; SBh[lk4+3][lr]=wh0.w;
        SBh[lk4+8][lr]=wh1.x; SBh[lk4+9][lr]=wh1.y; SBh[lk4+10][lr]=wh1.z; SBh[lk4+11][lr]=wh1.w;
        SBl[lk4+0][lr]=wl0.x; SBl[lk4+1][lr]=wl0.y; SBl[lk4+2][lr]=wl0.z; SBl[lk4+3][lr]=wl0.w;
        SBl[lk4+8][lr]=wl1.x; SBl[lk4+9][lr]=wl1.y; SBl[lk4+10][lr]=wl1.z; SBl[lk4+11][lr]=wl1.w;
        __syncthreads();
        if (kt + 16 < K) {
            int o = kt + 16;
            ah0 = *(const float4*)(Ahp + o); ah1 = *(const float4*)(Ahp + o + 8);
            al0 = *(const float4*)(Alp + o); al1 = *(const float4*)(Alp + o + 8);
            wh0 = *(const float4*)(Whp + o); wh1 = *(const float4*)(Whp + o + 8);
            wl0 = *(const float4*)(Wlp + o); wl1 = *(const float4*)(Wlp + o + 8);
        }
#pragma unroll
        for (int ks = 0; ks < 16; ks += 8) {
            float af[2][4][4];
#pragma unroll
            for (int mi = 0; mi < 4; mi++) {
                int mr = moff + mi * 16 + g;
                af[0][mi][0] = SAh[ks+tg][mr];   af[0][mi][1] = SAh[ks+tg][mr+8];
                af[0][mi][2] = SAh[ks+tg+4][mr]; af[0][mi][3] = SAh[ks+tg+4][mr+8];
                af[1][mi][0] = SAl[ks+tg][mr];   af[1][mi][1] = SAl[ks+tg][mr+8];
                af[1][mi][2] = SAl[ks+tg+4][mr]; af[1][mi][3] = SAl[ks+tg+4][mr+8];
            }
#pragma unroll
            for (int ni = 0; ni < 4; ni++) {
                int nc = noff + ni * 8 + g;
                float bh0 = SBh[ks+tg][nc], bh1 = SBh[ks+tg+4][nc];
                float bl0 = SBl[ks+tg][nc], bl1 = SBl[ks+tg+4][nc];
#pragma unroll
                for (int mi = 0; mi < 4; mi++) {
                    mma_tf32(c_[mi][ni], af[0][mi], bh0, bh1);
                    mma_tf32(c_[mi][ni], af[0][mi], bl0, bl1);
                    mma_tf32(c_[mi][ni], af[1][mi], bh0, bh1);
                }
            }
        }
        __syncthreads();
    }

    // epilogue
#pragma unroll
    for (int ni = 0; ni < 4; ni++) {
        int cc = n0 + noff + ni * 8 + 2 * tg;
        float bx = bias[cc], by = bias[cc + 1];
        if (bias2) { bx += bias2[cc]; by += bias2[cc + 1]; }
#pragma unroll
        for (int mi = 0; mi < 4; mi++) {
            size_t r0 = (size_t)(m0 + moff + mi * 16 + g);
            size_t r1 = r0 + 8;
            float v0 = c_[mi][ni][0] + bx, v1 = c_[mi][ni][1] + by;
            float v2 = c_[mi][ni][2] + bx, v3 = c_[mi][ni][3] + by;
            if (ACT) {
                v0 = fmaxf(v0, 0.f); v1 = fmaxf(v1, 0.f);
                v2 = fmaxf(v2, 0.f); v3 = fmaxf(v3, 0.f);
            }
            if (SPLIT_OUT) {
                float h0,l0_,h1,l1_,h2,l2_,h3,l3_;
                split2(v0,h0,l0_); split2(v1,h1,l1_);
                split2(v2,h2,l2_); split2(v3,h3,l3_);
                *(float2*)(Ch + r0*N + cc) = make_float2(h0, h1);
                *(float2*)(Cl + r0*N + cc) = make_float2(l0_, l1_);
                *(float2*)(Ch + r1*N + cc) = make_float2(h2, h3);
                *(float2*)(Cl + r1*N + cc) = make_float2(l2_, l3_);
            } else {
                *(float2*)(C + r0*N + cc) = make_float2(v0, v1);
                *(float2*)(C + r1*N + cc) = make_float2(v2, v3);
            }
        }
    }
}

// ---------------- bin encoder ----------------
__global__ void bin_enc_kernel(const float* __restrict__ bin,
                               const float* __restrict__ W1, const float* __restrict__ b1,
                               const float* __restrict__ W2, const float* __restrict__ b2,
                               float* __restrict__ bb)
{
    __shared__ float h1s[64];
    int b = blockIdx.x, j = threadIdx.x;
    float x0 = bin[b*2], x1 = bin[b*2+1];
    float h = fmaxf(fmaf(x0, W1[j*2], fmaf(x1, W1[j*2+1], b1[j])), 0.f);
    h1s[j] = h;
    __syncthreads();
    float acc = b2[j];
#pragma unroll 8
    for (int k = 0; k < 64; k++) acc = fmaf(h1s[k], W2[j*64 + k], acc);
    bb[b*64 + j] = acc;
}

// ---------------- concat: x = [p | bb | pos], writes plain + split ----------
__global__ void concat_kernel(const float* __restrict__ p, const float* __restrict__ bb,
                              const float* __restrict__ pos, float* __restrict__ x,
                              float* __restrict__ xhi, float* __restrict__ xlo)
{
    int idx = blockIdx.x * 128 + threadIdx.x;
    int r = idx >> 6, c4 = idx & 63;
    int b = r >> 8, s = r & 255;
    float4 v;
    if (c4 < 32)      v = ((const float4*)(p   + (size_t)r*128))[c4];
    else if (c4 < 48) v = ((const float4*)(bb  + (size_t)b*64))[c4-32];
    else              v = ((const float4*)(pos + (size_t)s*64))[c4-48];
    float4 h, l;
    split2(v.x,h.x,l.x); split2(v.y,h.y,l.y); split2(v.z,h.z,l.z); split2(v.w,h.w,l.w);
    ((float4*)(x   + (size_t)r*256))[c4] = v;
    ((float4*)(xhi + (size_t)r*256))[c4] = h;
    ((float4*)(xlo + (size_t)r*256))[c4] = l;
}

// ---------------- attention: one CTA per (b, head); split output -----------
__global__ __launch_bounds__(128, 1) void attn_kernel(const float* __restrict__ qkv,
                                                      float* __restrict__ ohi,
                                                      float* __restrict__ olo)
{
    extern __shared__ float sm[];
    float* Ks = sm;
    float* Vs = sm + 256*32;
    int b = blockIdx.x >> 3, h = blockIdx.x & 7;
    int tid = threadIdx.x;
    const float scale = 0.17677669529663687f;

    for (int r = tid; r < 256; r += 128) {
        const float4* ksrc = (const float4*)(qkv + (size_t)(b*256 + r)*768 + 256 + h*32);
        const float4* vsrc = (const float4*)(qkv + (size_t)(b*256 + r)*768 + 512 + h*32);
        float4* kd = (float4*)(Ks + r*32);
        float4* vd = (float4*)(Vs + r*32);
#pragma unroll
        for (int i = 0; i < 8; i++) { kd[i] = ksrc[i]; vd[i] = vsrc[i]; }
    }
    float q0[32], q1[32], acc0[32], acc1[32];
    {
        const float4* q0f = (const float4*)(qkv + (size_t)(b*256 + tid)*768 + h*32);
        const float4* q1f = (const float4*)(qkv + (size_t)(b*256 + tid + 128)*768 + h*32);
#pragma unroll
        for (int i = 0; i < 8; i++) {
            float4 t0 = q0f[i], t1 = q1f[i];
            q0[i*4+0]=t0.x; q0[i*4+1]=t0.y; q0[i*4+2]=t0.z; q0[i*4+3]=t0.w;
            q1[i*4+0]=t1.x; q1[i*4+1]=t1.y; q1[i*4+2]=t1.z; q1[i*4+3]=t1.w;
        }
    }
#pragma unroll
    for (int i = 0; i < 32; i++) { acc0[i] = 0.f; acc1[i] = 0.f; }
    __syncthreads();

    float l0 = 0.f, l1 = 0.f;
    for (int k = 0; k < 256; k++) {
        float s0 = 0.f, s1 = 0.f;
        const float4* kr = (const float4*)(Ks + k*32);
#pragma unroll
        for (int i4 = 0; i4 < 8; i4++) {
            float4 kv = kr[i4];
            s0 = fmaf(q0[i4*4+0], kv.x, s0); s0 = fmaf(q0[i4*4+1], kv.y, s0);
            s0 = fmaf(q0[i4*4+2], kv.z, s0); s0 = fmaf(q0[i4*4+3], kv.w, s0);
            s1 = fmaf(q1[i4*4+0], kv.x, s1); s1 = fmaf(q1[i4*4+1], kv.y, s1);
            s1 = fmaf(q1[i4*4+2], kv.z, s1); s1 = fmaf(q1[i4*4+3], kv.w, s1);
        }
        float p0 = __expf(s0 * scale), p1 = __expf(s1 * scale);
        l0 += p0; l1 += p1;
        const float4* vr = (const float4*)(Vs + k*32);
#pragma unroll
        for (int i4 = 0; i4 < 8; i4++) {
            float4 vv = vr[i4];
            acc0[i4*4+0] = fmaf(p0, vv.x, acc0[i4*4+0]);
            acc0[i4*4+1] = fmaf(p0, vv.y, acc0[i4*4+1]);
            acc0[i4*4+2] = fmaf(p0, vv.z, acc0[i4*4+2]);
            acc0[i4*4+3] = fmaf(p0, vv.w, acc0[i4*4+3]);
            acc1[i4*4+0] = fmaf(p1, vv.x, acc1[i4*4+0]);
            acc1[i4*4+1] = fmaf(p1, vv.y, acc1[i4*4+1]);
            acc1[i4*4+2] = fmaf(p1, vv.z, acc1[i4*4+2]);
            acc1[i4*4+3] = fmaf(p1, vv.w, acc1[i4*4+3]);
        }
    }
    float inv0 = __fdividef(1.f, l0), inv1 = __fdividef(1.f, l1);
    size_t base0 = ((size_t)(b*256 + tid)*256 + h*32) >> 2;
    size_t base1 = ((size_t)(b*256 + tid + 128)*256 + h*32) >> 2;
#pragma unroll
    for (int i4 = 0; i4 < 8; i4++) {
        float4 r0, r1, h0, l0v, h1, l1v;
        r0.x = acc0[i4*4+0]*inv0; r0.y = acc0[i4*4+1]*inv0;
        r0.z = acc0[i4*4+2]*inv0; r0.w = acc0[i4*4+3]*inv0;
        r1.x = acc1[i4*4+0]*inv1; r1.y = acc1[i4*4+1]*inv1;
        r1.z = acc1[i4*4+2]*inv1; r1.w = acc1[i4*4+3]*inv1;
        split2(r0.x,h0.x,l0v.x); split2(r0.y,h0.y,l0v.y);
        split2(r0.z,h0.z,l0v.z); split2(r0.w,h0.w,l0v.w);
        split2(r1.x,h1.x,l1v.x); split2(r1.y,h1.y,l1v.y);
        split2(r1.z,h1.z,l1v.z); split2(r1.w,h1.w,l1v.w);
        ((float4*)ohi)[base0 + i4] = h0; ((float4*)olo)[base0 + i4] = l0v;
        ((float4*)ohi)[base1 + i4] = h1; ((float4*)olo)[base1 + i4] = l1v;
    }
}

// ---------------- residual + LayerNorm, writes plain + split ---------------
__global__ void add_ln_kernel(const float* __restrict__ x, const float* __restrict__ y,
                              const float* __restrict__ g, const float* __restrict__ be,
                              float* __restrict__ out,
                              float* __restrict__ ohi, float* __restrict__ olo)
{
    int warp = threadIdx.x >> 5, lane = threadIdx.x & 31;
    size_t row = (size_t)blockIdx.x * 8 + warp;
    const float4* xr = (const float4*)(x + row*256);
    const float4* yr = (const float4*)(y + row*256);
    float4 a0 = xr[lane*2], a1 = xr[lane*2+1];
    float4 c0 = yr[lane*2], c1 = yr[lane*2+1];
    float v[8];
    v[0]=a0.x+c0.x; v[1]=a0.y+c0.y; v[2]=a0.z+c0.z; v[3]=a0.w+c0.w;
    v[4]=a1.x+c1.x; v[5]=a1.y+c1.y; v[6]=a1.z+c1.z; v[7]=a1.w+c1.w;
    float s = 0.f, s2 = 0.f;
#pragma unroll
    for (int i = 0; i < 8; i++) { s += v[i]; s2 = fmaf(v[i], v[i], s2); }
#pragma unroll
    for (int o = 16; o > 0; o >>= 1) {
        s  += __shfl_xor_sync(0xffffffffu, s,  o);
        s2 += __shfl_xor_sync(0xffffffffu, s2, o);
    }
    float mean = s * (1.f/256.f);
    float var  = s2 * (1.f/256.f) - mean*mean;
    float rstd = rsqrtf(var + 1e-5f);
    const float4* gf = (const float4*)(g + lane*8);
    const float4* bf = (const float4*)(be + lane*8);
    float4 g0 = gf[0], g1 = gf[1], b0 = bf[0], b1 = bf[1];
    float4 r0, r1;
    r0.x = (v[0]-mean)*rstd*g0.x + b0.x; r0.y = (v[1]-mean)*rstd*g0.y + b0.y;
    r0.z = (v[2]-mean)*rstd*g0.z + b0.z; r0.w = (v[3]-mean)*rstd*g0.w + b0.w;
    r1.x = (v[4]-mean)*rstd*g1.x + b1.x; r1.y = (v[5]-mean)*rstd*g1.y + b1.y;
    r1.z = (v[6]-mean)*rstd*g1.z + b1.z; r1.w = (v[7]-mean)*rstd*g1.w + b1.w;
    float4 h0, l0v, h1, l1v;
    split2(r0.x,h0.x,l0v.x); split2(r0.y,h0.y,l0v.y);
    split2(r0.z,h0.z,l0v.z); split2(r0.w,h0.w,l0v.w);
    split2(r1.x,h1.x,l1v.x); split2(r1.y,h1.y,l1v.y);
    split2(r1.z,h1.z,l1v.z); split2(r1.w,h1.w,l1v.w);
    ((float4*)(out + row*256))[lane*2]   = r0;
    ((float4*)(out + row*256))[lane*2+1] = r1;
    ((float4*)(ohi + row*256))[lane*2]   = h0;
    ((float4*)(ohi + row*256))[lane*2+1] = h1;
    ((float4*)(olo + row*256))[lane*2]   = l0v;
    ((float4*)(olo + row*256))[lane*2+1] = l1v;
}

// ---------------- gather teacher-forced LSTM inputs (split out) ------------
__global__ void gather_kernel(const float* __restrict__ enc, const int* __restrict__ target,
                              float* __restrict__ xhi, float* __restrict__ xlo)
{
    int idx = blockIdx.x * 256 + threadIdx.x;
    int r = idx >> 6, c4 = idx & 63;
    int t = r >> 5, b = r & 31;
    float4 val = make_float4(0.f, 0.f, 0.f, 0.f);
    if (t > 0) {
        int tgt = target[b*256 + t - 1];
        val = ((const float4*)(enc + (size_t)(b*256 + tgt)*256))[c4];
    }
    float4 h, l;
    split2(val.x,h.x,l.x); split2(val.y,h.y,l.y);
    split2(val.z,h.z,l.z); split2(val.w,h.w,l.w);
    ((float4*)(xhi + (size_t)r*256))[c4] = h;
    ((float4*)(xlo + (size_t)r*256))[c4] = l;
}

// ---------------- zero the lstm step counters (every replay) ----------------
__global__ void lstm_init_kernel(int* __restrict__ cnt)
{
    int idx = blockIdx.x * 256 + threadIdx.x;
    if (idx < 32*256) cnt[idx] = 0;
}

// ---------------- LSTM: 256 CTAs, Whh in registers; split h output ---------
__global__ __launch_bounds__(256, 1) void lstm_kernel(
    const float* __restrict__ gin,   // [256*32][1024] row t*32+b
    const float* __restrict__ Whh,   // [1024][256]
    float* __restrict__ hallhi, float* __restrict__ halllo,
    float* __restrict__ hbuf,        // [2][32][256]
    int* __restrict__ cnt)           // [32][256]
{
    __shared__ float h_s[256];
    __shared__ float g_s[128];
    int b = blockIdx.x >> 3, part = blockIdx.x & 7;
    int tid = threadIdx.x;
    int p = tid >> 1, half = tid & 1;
    int gate = p >> 5, jj = p & 31;
    int col = gate * 256 + part * 32 + jj;

    float w[128];
    {
        const float4* wsrc = (const float4*)(Whh + (size_t)col * 256 + half * 128);
#pragma unroll
        for (int i = 0; i < 32; i++) {
            float4 v = wsrc[i];
            w[i*4+0]=v.x; w[i*4+1]=v.y; w[i*4+2]=v.z; w[i*4+3]=v.w;
        }
    }
    float c = 0.f;
    if (tid < 256) h_s[tid] = 0.f;
    __syncthreads();

    volatile int* vcnt = cnt + b * 256;
    for (int t = 0; t < 256; t++) {
        if (t > 0) {
            if (tid == 0) { while (vcnt[t-1] < LSTM_PARTS) { } }
            __syncthreads();
            const float4* hsrc = (const float4*)(hbuf + ((size_t)((t & 1) * 32 + b)) * 256);
            if (tid < 64) *(float4*)&h_s[tid*4] = __ldcg(hsrc + tid);
            __syncthreads();
        }
        float a0 = 0.f, a1 = 0.f, a2 = 0.f, a3 = 0.f;
        const float4* h4 = (const float4*)&h_s[half * 128];
#pragma unroll
        for (int k4 = 0; k4 < 32; k4 += 4) {
            float4 h0 = h4[k4], h1 = h4[k4+1], h2 = h4[k4+2], h3 = h4[k4+3];
            a0 = fmaf(w[k4*4+0],  h0.x, a0); a0 = fmaf(w[k4*4+1],  h0.y, a0);
            a0 = fmaf(w[k4*4+2],  h0.z, a0); a0 = fmaf(w[k4*4+3],  h0.w, a0);
            a1 = fmaf(w[k4*4+4],  h1.x, a1); a1 = fmaf(w[k4*4+5],  h1.y, a1);
            a1 = fmaf(w[k4*4+6],  h1.z, a1); a1 = fmaf(w[k4*4+7],  h1.w, a1);
            a2 = fmaf(w[k4*4+8],  h2.x, a2); a2 = fmaf(w[k4*4+9],  h2.y, a2);
            a2 = fmaf(w[k4*4+10], h2.z, a2); a2 = fmaf(w[k4*4+11], h2.w, a2);
            a3 = fmaf(w[k4*4+12], h3.x, a3); a3 = fmaf(w[k4*4+13], h3.y, a3);
            a3 = fmaf(w[k4*4+14], h3.z, a3); a3 = fmaf(w[k4*4+15], h3.w, a3);
        }
        float acc = (a0 + a1) + (a2 + a3);
        acc += __shfl_xor_sync(0xffffffffu, acc, 1);
        if (half == 0) {
            float gv = __ldcg(gin + ((size_t)(t*32 + b))*1024 + col);
            g_s[p] = acc + gv;
        }
        __syncthreads();
        if (tid < 32) {
            float gi = g_s[tid], gf = g_s[32+tid], gg = g_s[64+tid], go = g_s[96+tid];
            c = sigf(gf) * c + sigf(gi) * tanh_acc(gg);
            float h = sigf(go) * tanh_acc(c);
            int colh = part*32 + tid;
            hbuf[((size_t)(((t+1) & 1) * 32 + b))*256 + colh] = h;
            float hh, hl; split2(h, hh, hl);
            size_t oidx = ((size_t)(t*32 + b))*256 + colh;
            hallhi[oidx] = hh;
            halllo[oidx] = hl;
        }
        __threadfence();
        __syncthreads();
        if (tid == 0) atomicAdd(cnt + b*256 + t, 1);
    }
}

// ---------------- logits ----------------
__global__ __launch_bounds__(256, 1) void logits_kernel(
    const float* __restrict__ hp, const float* __restrict__ ep,
    const float* __restrict__ v, float* __restrict__ out)
{
    extern __shared__ float sm[];
    float (*hps)[260] = (float(*)[260])sm;
    float (*eps)[260] = (float(*)[260])(sm + 32*260);
    float* vs = sm + 64*260;
    int b = blockIdx.z, tt = blockIdx.y*32, it = blockIdx.x*32;
    int tid = threadIdx.x;
    for (int idx = tid; idx < 32*64; idx += 256) {
        int r = idx >> 6, c4 = idx & 63;
        *(float4*)&hps[r][c4*4] = ((const float4*)(hp + ((size_t)(tt+r)*32 + b)*256))[c4];
        *(float4*)&eps[r][c4*4] = ((const float4*)(ep + ((size_t)b*256 + it + r)*256))[c4];
    }
    if (tid < 64) *(float4*)&vs[tid*4] = ((const float4*)v)[tid];
    __syncthreads();
    int ti = (tid >> 4) * 2, ii = (tid & 15) * 2;
    float s00=0.f, s01=0.f, s10=0.f, s11=0.f;
    for (int j = 0; j < 256; j++) {
        float vj = vs[j];
        float h0 = hps[ti][j], h1 = hps[ti+1][j];
        float e0 = eps[ii][j], e1 = eps[ii+1][j];
        s00 = fmaf(vj, tanh_approx(h0+e0), s00);
        s01 = fmaf(vj, tanh_approx(h0+e1), s01);
        s10 = fmaf(vj, tanh_approx(h1+e0), s10);
        s11 = fmaf(vj, tanh_approx(h1+e1), s11);
    }
    size_t base = ((size_t)b*256 + tt + ti)*256 + it + ii;
    out[base]       = s00; out[base+1]   = s01;
    out[base+256]   = s10; out[base+257] = s11;
}

// ---------------- host ----------------
extern "C" void kernel_launch(void* const* d_in, const int* in_sizes, int n_in,
                              void* d_out, int out_size)
{
    const float* parts    = (const float*)d_in[0];
    const float* bin_info = (const float*)d_in[1];
    const int*   target   = (const int*)  d_in[2];
    const float* pe_W1 = (const float*)d_in[3];
    const float* pe_b1 = (const float*)d_in[4];
    const float* pe_W2 = (const float*)d_in[5];
    const float* pe_b2 = (const float*)d_in[6];
    const float* be_W1 = (const float*)d_in[7];
    const float* be_b1 = (const float*)d_in[8];
    const float* be_W2 = (const float*)d_in[9];
    const float* be_b2 = (const float*)d_in[10];
    const float* pos_emb = (const float*)d_in[11];
    const float* tr_Wqkv = (const float*)d_in[12];
    const float* tr_bqkv = (const float*)d_in[13];
    const float* tr_Wo   = (const float*)d_in[14];
    const float* tr_bo   = (const float*)d_in[15];
    const float* tr_ln1_g = (const float*)d_in[16];
    const float* tr_ln1_b = (const float*)d_in[17];
    const float* tr_ff_W1 = (const float*)d_in[18];
    const float* tr_ff_b1 = (const float*)d_in[19];
    const float* tr_ff_W2 = (const float*)d_in[20];
    const float* tr_ff_b2 = (const float*)d_in[21];
    const float* tr_ln2_g = (const float*)d_in[22];
    const float* tr_ln2_b = (const float*)d_in[23];
    const float* lstm_Wih = (const float*)d_in[24];
    const float* lstm_Whh = (const float*)d_in[25];
    const float* lstm_bih = (const float*)d_in[26];
    const float* lstm_bhh = (const float*)d_in[27];
    const float* ptr_W = (const float*)d_in[28];
    const float* ptr_b = (const float*)d_in[29];
    const float* ptr_v = (const float*)d_in[30];
    float* out = (float*)d_out;

    float *x_, *qkv_, *tmp_, *bb_, *ep_, *gin_, *hp_, *hbuf_;
    float *whi_, *wlo_, *phi_, *plo_, *xhi_, *xlo_, *athi_, *atlo_;
    float *ffhi_, *fflo_, *xihi_, *xilo_, *hahi_, *halo_;
    int* cnt_;
    cudaGetSymbolAddress((void**)&x_,    g_x);
    cudaGetSymbolAddress((void**)&qkv_,  g_qkv);
    cudaGetSymbolAddress((void**)&tmp_,  g_tmp);
    cudaGetSymbolAddress((void**)&bb_,   g_bb);
    cudaGetSymbolAddress((void**)&ep_,   g_eproj);
    cudaGetSymbolAddress((void**)&gin_,  g_gin);
    cudaGetSymbolAddress((void**)&hp_,   g_hp);
    cudaGetSymbolAddress((void**)&hbuf_, g_hbuf);
    cudaGetSymbolAddress((void**)&cnt_,  g_cnt);
    cudaGetSymbolAddress((void**)&whi_,  g_whi);
    cudaGetSymbolAddress((void**)&wlo_,  g_wlo);
    cudaGetSymbolAddress((void**)&phi_,  g_phi);
    cudaGetSymbolAddress((void**)&plo_,  g_plo);
    cudaGetSymbolAddress((void**)&xhi_,  g_xhi);
    cudaGetSymbolAddress((void**)&xlo_,  g_xlo);
    cudaGetSymbolAddress((void**)&athi_, g_athi);
    cudaGetSymbolAddress((void**)&atlo_, g_atlo);
    cudaGetSymbolAddress((void**)&ffhi_, g_ffhi);
    cudaGetSymbolAddress((void**)&fflo_, g_fflo);
    cudaGetSymbolAddress((void**)&xihi_, g_xihi);
    cudaGetSymbolAddress((void**)&xilo_, g_xilo);
    cudaGetSymbolAddress((void**)&hahi_, g_hahi);
    cudaGetSymbolAddress((void**)&halo_, g_halo);

    cudaFuncSetAttribute(attn_kernel,   cudaFuncAttributeMaxDynamicSharedMemorySize, 65536);
    cudaFuncSetAttribute(logits_kernel, cudaFuncAttributeMaxDynamicSharedMemorySize, 69632);

    // weight + input splits
    split_kernel<<<8,    256>>>(pe_W1,    whi_+OFF_PEW1, wlo_+OFF_PEW1, 2048);
    split_kernel<<<64,   256>>>(pe_W2,    whi_+OFF_PEW2, wlo_+OFF_PEW2, 16384);
    split_kernel<<<2304, 256>>>(tr_Wqkv,  whi_+OFF_WQKV, wlo_+OFF_WQKV, 589824);
    split_kernel<<<768,  256>>>(tr_Wo,    whi_+OFF_WO,   wlo_+OFF_WO,   196608);
    split_kernel<<<1536, 256>>>(tr_ff_W1, whi_+OFF_FFW1, wlo_+OFF_FFW1, 393216);
    split_kernel<<<1536, 256>>>(tr_ff_W2, whi_+OFF_FFW2, wlo_+OFF_FFW2, 393216);
    split_kernel<<<1024, 256>>>(lstm_Wih, whi_+OFF_WIH,  wlo_+OFF_WIH,  262144);
    split_kernel<<<256,  256>>>(ptr_W,    whi_+OFF_PTRW, wlo_+OFF_PTRW, 65536);
    split_kernel<<<512,  256>>>(parts,    phi_, plo_, 131072);

    // encoders
    bin_enc_kernel<<<32, 64>>>(bin_info, be_W1, be_b1, be_W2, be_b2, bb_);
    tgemm<1,1><<<dim3(1,64), 256>>>(phi_, plo_, whi_+OFF_PEW1, wlo_+OFF_PEW1,
                                    pe_b1, nullptr, nullptr, athi_, atlo_, ROWS_, 128, 16);
    tgemm<0,0><<<dim3(1,64), 256>>>(athi_, atlo_, whi_+OFF_PEW2, wlo_+OFF_PEW2,
                                    pe_b2, nullptr, tmp_, nullptr, nullptr, ROWS_, 128, 128);
    concat_kernel<<<4096, 128>>>(tmp_, bb_, pos_emb, x_, xhi_, xlo_);

    // transformer layers
    for (int l = 0; l < 3; l++) {
        tgemm<0,0><<<dim3(6,64), 256>>>(xhi_, xlo_,
            whi_+OFF_WQKV + (size_t)l*196608, wlo_+OFF_WQKV + (size_t)l*196608,
            tr_bqkv + l*768, nullptr, qkv_, nullptr, nullptr, ROWS_, 768, 256);
        attn_kernel<<<256, 128, 65536>>>(qkv_, athi_, atlo_);
        tgemm<0,0><<<dim3(2,64), 256>>>(athi_, atlo_,
            whi_+OFF_WO + (size_t)l*65536, wlo_+OFF_WO + (size_t)l*65536,
            tr_bo + l*256, nullptr, tmp_, nullptr, nullptr, ROWS_, 256, 256);
        add_ln_kernel<<<1024, 256>>>(x_, tmp_, tr_ln1_g + l*256, tr_ln1_b + l*256,
                                     x_, xhi_, xlo_);
        tgemm<1,1><<<dim3(4,64), 256>>>(xhi_, xlo_,
            whi_+OFF_FFW1 + (size_t)l*131072, wlo_+OFF_FFW1 + (size_t)l*131072,
            tr_ff_b1 + l*512, nullptr, nullptr, ffhi_, fflo_, ROWS_, 512, 256);
        tgemm<0,0><<<dim3(2,64), 256>>>(ffhi_, fflo_,
            whi_+OFF_FFW2 + (size_t)l*131072, wlo_+OFF_FFW2 + (size_t)l*131072,
            tr_ff_b2 + l*256, nullptr, tmp_, nullptr, nullptr, ROWS_, 256, 512);
        add_ln_kernel<<<1024, 256>>>(x_, tmp_, tr_ln2_g + l*256, tr_ln2_b + l*256,
                                     x_, xhi_, xlo_);
    }

    // pointer decode
    tgemm<0,0><<<dim3(2,64), 256>>>(xhi_, xlo_, whi_+OFF_PTRW, wlo_+OFF_PTRW,
                                    ptr_b, nullptr, ep_, nullptr, nullptr, ROWS_, 256, 256);
    gather_kernel<<<2048, 256>>>(x_, target, xihi_, xilo_);
    tgemm<0,0><<<dim3(8,64), 256>>>(xihi_, xilo_, whi_+OFF_WIH, wlo_+OFF_WIH,
                                    lstm_bih, lstm_bhh, gin_, nullptr, nullptr, ROWS_, 1024, 256);
    lstm_init_kernel<<<32, 256>>>(cnt_);
    lstm_kernel<<<256, 256>>>(gin_, lstm_Whh, hahi_, halo_, hbuf_, cnt_);
    tgemm<0,0><<<dim3(2,64), 256>>>(hahi_, halo_, whi_+OFF_PTRW, wlo_+OFF_PTRW,
                                    ptr_b, nullptr, hp_, nullptr, nullptr, ROWS_, 256, 256);
    logits_kernel<<<dim3(8,8,32), 256, 69632>>>(hp_, ep_, ptr_v, out);
}

// round 6
// speedup vs baseline: 5.0378x; 1.2809x over previous
#include <cuda_runtime.h>
#include <cuda_fp16.h>
#include <cuda_bf16.h>
#include <cstdint>

#define ROWS_ 8192
#define LSTM_PARTS 8

// weight-split buffer offsets (elements)
#define OFF_PEW1 0
#define OFF_PEW2 2048
#define OFF_WQKV 18432
#define OFF_WO   608256
#define OFF_FFW1 804864
#define OFF_FFW2 1198080
#define OFF_WIH  1591296
#define OFF_PTRW 1853440
#define W_TOTAL  1918976

// ---------------- device scratch ----------------
__device__ float g_x    [ROWS_*256];
__device__ float g_qkv  [ROWS_*768];
__device__ float g_tmp  [ROWS_*256];
__device__ float g_bb   [32*64];
__device__ float g_eproj[ROWS_*256];
__device__ float g_gin  [ROWS_*1024];
__device__ float g_hp   [ROWS_*256];
__device__ float g_hbuf [2*32*256];
__device__ int   g_cnt  [32*256];
// fp16 split pairs
__device__ __half g_whi[W_TOTAL], g_wlo[W_TOTAL];
__device__ __half g_phi[ROWS_*16],  g_plo[ROWS_*16];
__device__ __half g_xhi[ROWS_*256], g_xlo[ROWS_*256];
__device__ __half g_athi[ROWS_*256], g_atlo[ROWS_*256];
__device__ __half g_ffhi[ROWS_*512], g_fflo[ROWS_*512];
__device__ __half g_xihi[ROWS_*256], g_xilo[ROWS_*256];
__device__ __half g_hahi[ROWS_*256], g_halo[ROWS_*256];

__device__ __forceinline__ float sigf(float x) {
    return __fdividef(1.f, 1.f + __expf(-x));
}
__device__ __forceinline__ float tanh_acc(float x) {
    float xx = fminf(fmaxf(x, -15.f), 15.f);
    float e  = __expf(2.f * xx);
    return __fdividef(e - 1.f, e + 1.f);
}
__device__ __forceinline__ float tanh_approx(float x) {
    float y;
    asm("tanh.approx.f32 %0, %1;" : "=f"(y) : "f"(x));
    return y;
}
__device__ __forceinline__ void split2h(float x, __half& hi, __half& lo) {
    hi = __float2half_rn(x);
    lo = __float2half_rn(x - __half2float(hi));
}
__device__ __forceinline__ __half2 sp_hi2(float a, float b) {
    return __halves2half2(__float2half_rn(a), __float2half_rn(b));
}
__device__ __forceinline__ __half2 sp_lo2(float a, float b) {
    __half ha = __float2half_rn(a), hb = __float2half_rn(b);
    return __halves2half2(__float2half_rn(a - __half2float(ha)),
                          __float2half_rn(b - __half2float(hb)));
}

// ---------------- generic splitter ----------------
__global__ void split_kernel(const float* __restrict__ src, __half* __restrict__ hi,
                             __half* __restrict__ lo, int n)
{
    int i = blockIdx.x * 256 + threadIdx.x;
    if (i < n) { __half h, l; split2h(src[i], h, l); hi[i] = h; lo[i] = l; }
}

// ---------------- fp16 3-term split tensor-core GEMM ----------------
// C[M,N] = A[M,K] @ W[N,K]^T + bias (+bias2). M,N mult of 128; K mult of CHUNK.
__device__ __forceinline__ void mma_f16(float* c, const uint32_t* a,
                                        uint32_t b0, uint32_t b1) {
    asm volatile(
        "mma.sync.aligned.m16n8k16.row.col.f32.f16.f16.f32 "
        "{%0,%1,%2,%3}, {%4,%5,%6,%7}, {%8,%9}, {%0,%1,%2,%3};\n"
        : "+f"(c[0]), "+f"(c[1]), "+f"(c[2]), "+f"(c[3])
        : "r"(a[0]), "r"(a[1]), "r"(a[2]), "r"(a[3]), "r"(b0), "r"(b1));
}

#define STR_ 56   // smem row stride in halves: 112B = 28 banks -> conflict-free frags

template<int ACT, int SPLIT_OUT, int CHUNK>
__global__ __launch_bounds__(256, 1) void tgemm(
    const __half* __restrict__ Ah, const __half* __restrict__ Al,
    const __half* __restrict__ Wh, const __half* __restrict__ Wl,
    const float* __restrict__ bias, const float* __restrict__ bias2,
    float* __restrict__ C, __half* __restrict__ Ch, __half* __restrict__ Cl,
    int M, int N, int K)
{
    extern __shared__ __half smh[];
    __half* SA_h = smh;
    __half* SA_l = smh + 128*STR_;
    __half* SB_h = smh + 2*128*STR_;
    __half* SB_l = smh + 3*128*STR_;

    int tid = threadIdx.x;
    int m0 = blockIdx.y * 128, n0 = blockIdx.x * 128;
    int warp = tid >> 5, lane = tid & 31;
    int g = lane >> 2, tg = lane & 3;
    int moff = (warp >> 2) * 64, noff = (warp & 3) * 32;

    constexpr int F4 = CHUNK / 16;      // float4 (8 halves) per thread per matrix
    int row = tid >> 1;
    int fbase = (tid & 1) * F4;

    const float4* Ahp = (const float4*)(Ah + (size_t)(m0 + row) * K);
    const float4* Alp = (const float4*)(Al + (size_t)(m0 + row) * K);
    const float4* Whp = (const float4*)(Wh + (size_t)(n0 + row) * K);
    const float4* Wlp = (const float4*)(Wl + (size_t)(n0 + row) * K);

    float c_[4][4][4];
#pragma unroll
    for (int i = 0; i < 4; i++)
#pragma unroll
        for (int j = 0; j < 4; j++)
#pragma unroll
            for (int r = 0; r < 4; r++) c_[i][j][r] = 0.f;

    float4 pAh[F4], pAl[F4], pBh[F4], pBl[F4];
#pragma unroll
    for (int j = 0; j < F4; j++) {
        int fi = fbase + j;
        pAh[j] = Ahp[fi]; pAl[j] = Alp[fi];
        pBh[j] = Whp[fi]; pBl[j] = Wlp[fi];
    }

    for (int kt = 0; kt < K; kt += CHUNK) {
#pragma unroll
        for (int j = 0; j < F4; j++) {
            int fi = fbase + j;
            *(float4*)(SA_h + row*STR_ + fi*8) = pAh[j];
            *(float4*)(SA_l + row*STR_ + fi*8) = pAl[j];
            *(float4*)(SB_h + row*STR_ + fi*8) = pBh[j];
            *(float4*)(SB_l + row*STR_ + fi*8) = pBl[j];
        }
        __syncthreads();
        if (kt + CHUNK < K) {
            int ko = (kt + CHUNK) >> 3;
#pragma unroll
            for (int j = 0; j < F4; j++) {
                int fi = ko + fbase + j;
                pAh[j] = Ahp[fi]; pAl[j] = Alp[fi];
                pBh[j] = Whp[fi]; pBl[j] = Wlp[fi];
            }
        }
#pragma unroll
        for (int ks = 0; ks < CHUNK/16; ks++) {
            int kb = ks * 16 + 2 * tg;
            uint32_t ah[4][4], al[4][4];
#pragma unroll
            for (int mi = 0; mi < 4; mi++) {
                int r = (moff + mi*16 + g) * STR_;
                ah[mi][0] = *(const uint32_t*)(SA_h + r + kb);
                ah[mi][1] = *(const uint32_t*)(SA_h + r + 8*STR_ + kb);
                ah[mi][2] = *(const uint32_t*)(SA_h + r + kb + 8);
                ah[mi][3] = *(const uint32_t*)(SA_h + r + 8*STR_ + kb + 8);
                al[mi][0] = *(const uint32_t*)(SA_l + r + kb);
                al[mi][1] = *(const uint32_t*)(SA_l + r + 8*STR_ + kb);
                al[mi][2] = *(const uint32_t*)(SA_l + r + kb + 8);
                al[mi][3] = *(const uint32_t*)(SA_l + r + 8*STR_ + kb + 8);
            }
#pragma unroll
            for (int ni = 0; ni < 4; ni++) {
                int n = (noff + ni*8 + g) * STR_;
                uint32_t bh0 = *(const uint32_t*)(SB_h + n + kb);
                uint32_t bh1 = *(const uint32_t*)(SB_h + n + kb + 8);
                uint32_t bl0 = *(const uint32_t*)(SB_l + n + kb);
                uint32_t bl1 = *(const uint32_t*)(SB_l + n + kb + 8);
#pragma unroll
                for (int mi = 0; mi < 4; mi++) {
                    mma_f16(c_[mi][ni], ah[mi], bh0, bh1);
                    mma_f16(c_[mi][ni], ah[mi], bl0, bl1);
                    mma_f16(c_[mi][ni], al[mi], bh0, bh1);
                }
            }
        }
        __syncthreads();
    }

    // epilogue
#pragma unroll
    for (int ni = 0; ni < 4; ni++) {
        int cc = n0 + noff + ni * 8 + 2 * tg;
        float bx = bias[cc], by = bias[cc + 1];
        if (bias2) { bx += bias2[cc]; by += bias2[cc + 1]; }
#pragma unroll
        for (int mi = 0; mi < 4; mi++) {
            size_t r0 = (size_t)(m0 + moff + mi * 16 + g);
            size_t r1 = r0 + 8;
            float v0 = c_[mi][ni][0] + bx, v1 = c_[mi][ni][1] + by;
            float v2 = c_[mi][ni][2] + bx, v3 = c_[mi][ni][3] + by;
            if (ACT) {
                v0 = fmaxf(v0, 0.f); v1 = fmaxf(v1, 0.f);
                v2 = fmaxf(v2, 0.f); v3 = fmaxf(v3, 0.f);
            }
            if (SPLIT_OUT) {
                *(__half2*)(Ch + r0*N + cc) = sp_hi2(v0, v1);
                *(__half2*)(Cl + r0*N + cc) = sp_lo2(v0, v1);
                *(__half2*)(Ch + r1*N + cc) = sp_hi2(v2, v3);
                *(__half2*)(Cl + r1*N + cc) = sp_lo2(v2, v3);
            } else {
                *(float2*)(C + r0*N + cc) = make_float2(v0, v1);
                *(float2*)(C + r1*N + cc) = make_float2(v2, v3);
            }
        }
    }
}

// ---------------- bin encoder ----------------
__global__ void bin_enc_kernel(const float* __restrict__ bin,
                               const float* __restrict__ W1, const float* __restrict__ b1,
                               const float* __restrict__ W2, const float* __restrict__ b2,
                               float* __restrict__ bb)
{
    __shared__ float h1s[64];
    int b = blockIdx.x, j = threadIdx.x;
    float x0 = bin[b*2], x1 = bin[b*2+1];
    float h = fmaxf(fmaf(x0, W1[j*2], fmaf(x1, W1[j*2+1], b1[j])), 0.f);
    h1s[j] = h;
    __syncthreads();
    float acc = b2[j];
#pragma unroll 8
    for (int k = 0; k < 64; k++) acc = fmaf(h1s[k], W2[j*64 + k], acc);
    bb[b*64 + j] = acc;
}

// ---------------- concat: x = [p | bb | pos], plain + fp16 split -----------
__global__ void concat_kernel(const float* __restrict__ p, const float* __restrict__ bb,
                              const float* __restrict__ pos, float* __restrict__ x,
                              __half* __restrict__ xhi, __half* __restrict__ xlo)
{
    int idx = blockIdx.x * 128 + threadIdx.x;
    int r = idx >> 6, c4 = idx & 63;
    int b = r >> 8, s = r & 255;
    float4 v;
    if (c4 < 32)      v = ((const float4*)(p   + (size_t)r*128))[c4];
    else if (c4 < 48) v = ((const float4*)(bb  + (size_t)b*64))[c4-32];
    else              v = ((const float4*)(pos + (size_t)s*64))[c4-48];
    ((float4*)(x + (size_t)r*256))[c4] = v;
    __half2* ph = (__half2*)(xhi + (size_t)r*256);
    __half2* pl = (__half2*)(xlo + (size_t)r*256);
    ph[c4*2]   = sp_hi2(v.x, v.y); pl[c4*2]   = sp_lo2(v.x, v.y);
    ph[c4*2+1] = sp_hi2(v.z, v.w); pl[c4*2+1] = sp_lo2(v.z, v.w);
}

// ---------------- attention: one CTA per (b, head); fp16-split output ------
__global__ __launch_bounds__(128, 1) void attn_kernel(const float* __restrict__ qkv,
                                                      __half* __restrict__ ohi,
                                                      __half* __restrict__ olo)
{
    extern __shared__ float sm[];
    float* Ks = sm;
    float* Vs = sm + 256*32;
    int b = blockIdx.x >> 3, h = blockIdx.x & 7;
    int tid = threadIdx.x;
    const float scale = 0.17677669529663687f;

    for (int r = tid; r < 256; r += 128) {
        const float4* ksrc = (const float4*)(qkv + (size_t)(b*256 + r)*768 + 256 + h*32);
        const float4* vsrc = (const float4*)(qkv + (size_t)(b*256 + r)*768 + 512 + h*32);
        float4* kd = (float4*)(Ks + r*32);
        float4* vd = (float4*)(Vs + r*32);
#pragma unroll
        for (int i = 0; i < 8; i++) { kd[i] = ksrc[i]; vd[i] = vsrc[i]; }
    }
    float q0[32], q1[32], acc0[32], acc1[32];
    {
        const float4* q0f = (const float4*)(qkv + (size_t)(b*256 + tid)*768 + h*32);
        const float4* q1f = (const float4*)(qkv + (size_t)(b*256 + tid + 128)*768 + h*32);
#pragma unroll
        for (int i = 0; i < 8; i++) {
            float4 t0 = q0f[i], t1 = q1f[i];
            q0[i*4+0]=t0.x; q0[i*4+1]=t0.y; q0[i*4+2]=t0.z; q0[i*4+3]=t0.w;
            q1[i*4+0]=t1.x; q1[i*4+1]=t1.y; q1[i*4+2]=t1.z; q1[i*4+3]=t1.w;
        }
    }
#pragma unroll
    for (int i = 0; i < 32; i++) { acc0[i] = 0.f; acc1[i] = 0.f; }
    __syncthreads();

    float l0 = 0.f, l1 = 0.f;
    for (int k = 0; k < 256; k++) {
        float s0 = 0.f, s1 = 0.f;
        const float4* kr = (const float4*)(Ks + k*32);
#pragma unroll
        for (int i4 = 0; i4 < 8; i4++) {
            float4 kv = kr[i4];
            s0 = fmaf(q0[i4*4+0], kv.x, s0); s0 = fmaf(q0[i4*4+1], kv.y, s0);
            s0 = fmaf(q0[i4*4+2], kv.z, s0); s0 = fmaf(q0[i4*4+3], kv.w, s0);
            s1 = fmaf(q1[i4*4+0], kv.x, s1); s1 = fmaf(q1[i4*4+1], kv.y, s1);
            s1 = fmaf(q1[i4*4+2], kv.z, s1); s1 = fmaf(q1[i4*4+3], kv.w, s1);
        }
        float p0 = __expf(s0 * scale), p1 = __expf(s1 * scale);
        l0 += p0; l1 += p1;
        const float4* vr = (const float4*)(Vs + k*32);
#pragma unroll
        for (int i4 = 0; i4 < 8; i4++) {
            float4 vv = vr[i4];
            acc0[i4*4+0] = fmaf(p0, vv.x, acc0[i4*4+0]);
            acc0[i4*4+1] = fmaf(p0, vv.y, acc0[i4*4+1]);
            acc0[i4*4+2] = fmaf(p0, vv.z, acc0[i4*4+2]);
            acc0[i4*4+3] = fmaf(p0, vv.w, acc0[i4*4+3]);
            acc1[i4*4+0] = fmaf(p1, vv.x, acc1[i4*4+0]);
            acc1[i4*4+1] = fmaf(p1, vv.y, acc1[i4*4+1]);
            acc1[i4*4+2] = fmaf(p1, vv.z, acc1[i4*4+2]);
            acc1[i4*4+3] = fmaf(p1, vv.w, acc1[i4*4+3]);
        }
    }
    float inv0 = __fdividef(1.f, l0), inv1 = __fdividef(1.f, l1);
    __half2* oh0 = (__half2*)(ohi + (size_t)(b*256 + tid)*256 + h*32);
    __half2* ol0 = (__half2*)(olo + (size_t)(b*256 + tid)*256 + h*32);
    __half2* oh1 = (__half2*)(ohi + (size_t)(b*256 + tid + 128)*256 + h*32);
    __half2* ol1 = (__half2*)(olo + (size_t)(b*256 + tid + 128)*256 + h*32);
#pragma unroll
    for (int i4 = 0; i4 < 8; i4++) {
        float r0x = acc0[i4*4+0]*inv0, r0y = acc0[i4*4+1]*inv0;
        float r0z = acc0[i4*4+2]*inv0, r0w = acc0[i4*4+3]*inv0;
        float r1x = acc1[i4*4+0]*inv1, r1y = acc1[i4*4+1]*inv1;
        float r1z = acc1[i4*4+2]*inv1, r1w = acc1[i4*4+3]*inv1;
        oh0[i4*2]   = sp_hi2(r0x, r0y); ol0[i4*2]   = sp_lo2(r0x, r0y);
        oh0[i4*2+1] = sp_hi2(r0z, r0w); ol0[i4*2+1] = sp_lo2(r0z, r0w);
        oh1[i4*2]   = sp_hi2(r1x, r1y); ol1[i4*2]   = sp_lo2(r1x, r1y);
        oh1[i4*2+1] = sp_hi2(r1z, r1w); ol1[i4*2+1] = sp_lo2(r1z, r1w);
    }
}

// ---------------- residual + LayerNorm, plain + fp16 split -----------------
__global__ void add_ln_kernel(const float* __restrict__ x, const float* __restrict__ y,
                              const float* __restrict__ g, const float* __restrict__ be,
                              float* __restrict__ out,
                              __half* __restrict__ ohi, __half* __restrict__ olo)
{
    int warp = threadIdx.x >> 5, lane = threadIdx.x & 31;
    size_t row = (size_t)blockIdx.x * 8 + warp;
    const float4* xr = (const float4*)(x + row*256);
    const float4* yr = (const float4*)(y + row*256);
    float4 a0 = xr[lane*2], a1 = xr[lane*2+1];
    float4 c0 = yr[lane*2], c1 = yr[lane*2+1];
    float v[8];
    v[0]=a0.x+c0.x; v[1]=a0.y+c0.y; v[2]=a0.z+c0.z; v[3]=a0.w+c0.w;
    v[4]=a1.x+c1.x; v[5]=a1.y+c1.y; v[6]=a1.z+c1.z; v[7]=a1.w+c1.w;
    float s = 0.f, s2 = 0.f;
#pragma unroll
    for (int i = 0; i < 8; i++) { s += v[i]; s2 = fmaf(v[i], v[i], s2); }
#pragma unroll
    for (int o = 16; o > 0; o >>= 1) {
        s  += __shfl_xor_sync(0xffffffffu, s,  o);
        s2 += __shfl_xor_sync(0xffffffffu, s2, o);
    }
    float mean = s * (1.f/256.f);
    float var  = s2 * (1.f/256.f) - mean*mean;
    float rstd = rsqrtf(var + 1e-5f);
    const float4* gf = (const float4*)(g + lane*8);
    const float4* bf = (const float4*)(be + lane*8);
    float4 g0 = gf[0], g1 = gf[1], b0 = bf[0], b1 = bf[1];
    float r[8];
    r[0] = (v[0]-mean)*rstd*g0.x + b0.x; r[1] = (v[1]-mean)*rstd*g0.y + b0.y;
    r[2] = (v[2]-mean)*rstd*g0.z + b0.z; r[3] = (v[3]-mean)*rstd*g0.w + b0.w;
    r[4] = (v[4]-mean)*rstd*g1.x + b1.x; r[5] = (v[5]-mean)*rstd*g1.y + b1.y;
    r[6] = (v[6]-mean)*rstd*g1.z + b1.z; r[7] = (v[7]-mean)*rstd*g1.w + b1.w;
    ((float4*)(out + row*256))[lane*2]   = make_float4(r[0], r[1], r[2], r[3]);
    ((float4*)(out + row*256))[lane*2+1] = make_float4(r[4], r[5], r[6], r[7]);
    __half2* ph = (__half2*)(ohi + row*256);
    __half2* pl = (__half2*)(olo + row*256);
#pragma unroll
    for (int i = 0; i < 4; i++) {
        ph[lane*4 + i] = sp_hi2(r[i*2], r[i*2+1]);
        pl[lane*4 + i] = sp_lo2(r[i*2], r[i*2+1]);
    }
}

// ---------------- gather teacher-forced LSTM inputs (fp16 split) -----------
__global__ void gather_kernel(const float* __restrict__ enc, const int* __restrict__ target,
                              __half* __restrict__ xhi, __half* __restrict__ xlo)
{
    int idx = blockIdx.x * 256 + threadIdx.x;
    int r = idx >> 6, c4 = idx & 63;
    int t = r >> 5, b = r & 31;
    float4 val = make_float4(0.f, 0.f, 0.f, 0.f);
    if (t > 0) {
        int tgt = target[b*256 + t - 1];
        val = ((const float4*)(enc + (size_t)(b*256 + tgt)*256))[c4];
    }
    __half2* ph = (__half2*)(xhi + (size_t)r*256);
    __half2* pl = (__half2*)(xlo + (size_t)r*256);
    ph[c4*2]   = sp_hi2(val.x, val.y); pl[c4*2]   = sp_lo2(val.x, val.y);
    ph[c4*2+1] = sp_hi2(val.z, val.w); pl[c4*2+1] = sp_lo2(val.z, val.w);
}

// ---------------- zero the lstm step counters (every replay) ----------------
__global__ void lstm_init_kernel(int* __restrict__ cnt)
{
    int idx = blockIdx.x * 256 + threadIdx.x;
    if (idx < 32*256) cnt[idx] = 0;
}

// ---------------- LSTM: 256 CTAs, Whh in registers; fp16-split h out -------
__global__ __launch_bounds__(256, 1) void lstm_kernel(
    const float* __restrict__ gin,   // [256*32][1024] row t*32+b
    const float* __restrict__ Whh,   // [1024][256]
    __half* __restrict__ hallhi, __half* __restrict__ halllo,
    float* __restrict__ hbuf,        // [2][32][256]
    int* __restrict__ cnt)           // [32][256]
{
    __shared__ float h_s[256];
    __shared__ float g_s[128];
    int b = blockIdx.x >> 3, part = blockIdx.x & 7;
    int tid = threadIdx.x;
    int p = tid >> 1, half = tid & 1;
    int gate = p >> 5, jj = p & 31;
    int col = gate * 256 + part * 32 + jj;

    float w[128];
    {
        const float4* wsrc = (const float4*)(Whh + (size_t)col * 256 + half * 128);
#pragma unroll
        for (int i = 0; i < 32; i++) {
            float4 v = wsrc[i];
            w[i*4+0]=v.x; w[i*4+1]=v.y; w[i*4+2]=v.z; w[i*4+3]=v.w;
        }
    }
    float c = 0.f;
    if (tid < 256) h_s[tid] = 0.f;
    __syncthreads();

    volatile int* vcnt = cnt + b * 256;
    for (int t = 0; t < 256; t++) {
        if (t > 0) {
            if (tid == 0) { while (vcnt[t-1] < LSTM_PARTS) { } }
            __syncthreads();
            const float4* hsrc = (const float4*)(hbuf + ((size_t)((t & 1) * 32 + b)) * 256);
            if (tid < 64) *(float4*)&h_s[tid*4] = __ldcg(hsrc + tid);
            __syncthreads();
        }
        float a0 = 0.f, a1 = 0.f, a2 = 0.f, a3 = 0.f;
        const float4* h4 = (const float4*)&h_s[half * 128];
#pragma unroll
        for (int k4 = 0; k4 < 32; k4 += 4) {
            float4 h0 = h4[k4], h1 = h4[k4+1], h2 = h4[k4+2], h3 = h4[k4+3];
            a0 = fmaf(w[k4*4+0],  h0.x, a0); a0 = fmaf(w[k4*4+1],  h0.y, a0);
            a0 = fmaf(w[k4*4+2],  h0.z, a0); a0 = fmaf(w[k4*4+3],  h0.w, a0);
            a1 = fmaf(w[k4*4+4],  h1.x, a1); a1 = fmaf(w[k4*4+5],  h1.y, a1);
            a1 = fmaf(w[k4*4+6],  h1.z, a1); a1 = fmaf(w[k4*4+7],  h1.w, a1);
            a2 = fmaf(w[k4*4+8],  h2.x, a2); a2 = fmaf(w[k4*4+9],  h2.y, a2);
            a2 = fmaf(w[k4*4+10], h2.z, a2); a2 = fmaf(w[k4*4+11], h2.w, a2);
            a3 = fmaf(w[k4*4+12], h3.x, a3); a3 = fmaf(w[k4*4+13], h3.y, a3);
            a3 = fmaf(w[k4*4+14], h3.z, a3); a3 = fmaf(w[k4*4+15], h3.w, a3);
        }
        float acc = (a0 + a1) + (a2 + a3);
        acc += __shfl_xor_sync(0xffffffffu, acc, 1);
        if (half == 0) {
            float gv = __ldcg(gin + ((size_t)(t*32 + b))*1024 + col);
            g_s[p] = acc + gv;
        }
        __syncthreads();
        if (tid < 32) {
            float gi = g_s[tid], gf = g_s[32+tid], gg = g_s[64+tid], go = g_s[96+tid];
            c = sigf(gf) * c + sigf(gi) * tanh_acc(gg);
            float h = sigf(go) * tanh_acc(c);
            int colh = part*32 + tid;
            hbuf[((size_t)(((t+1) & 1) * 32 + b))*256 + colh] = h;
            __half hh, hl; split2h(h, hh, hl);
            size_t oidx = ((size_t)(t*32 + b))*256 + colh;
            hallhi[oidx] = hh;
            halllo[oidx] = hl;
        }
        __threadfence();
        __syncthreads();
        if (tid == 0) atomicAdd(cnt + b*256 + t, 1);
    }
}

// ---------------- logits ----------------
__global__ __launch_bounds__(256, 1) void logits_kernel(
    const float* __restrict__ hp, const float* __restrict__ ep,
    const float* __restrict__ v, float* __restrict__ out)
{
    extern __shared__ float sm[];
    float (*hps)[260] = (float(*)[260])sm;
    float (*eps)[260] = (float(*)[260])(sm + 32*260);
    float* vs = sm + 64*260;
    int b = blockIdx.z, tt = blockIdx.y*32, it = blockIdx.x*32;
    int tid = threadIdx.x;
    for (int idx = tid; idx < 32*64; idx += 256) {
        int r = idx >> 6, c4 = idx & 63;
        *(float4*)&hps[r][c4*4] = ((const float4*)(hp + ((size_t)(tt+r)*32 + b)*256))[c4];
        *(float4*)&eps[r][c4*4] = ((const float4*)(ep + ((size_t)b*256 + it + r)*256))[c4];
    }
    if (tid < 64) *(float4*)&vs[tid*4] = ((const float4*)v)[tid];
    __syncthreads();
    int ti = (tid >> 4) * 2, ii = (tid & 15) * 2;
    float s00=0.f, s01=0.f, s10=0.f, s11=0.f;
    for (int j = 0; j < 256; j++) {
        float vj = vs[j];
        float h0 = hps[ti][j], h1 = hps[ti+1][j];
        float e0 = eps[ii][j], e1 = eps[ii+1][j];
        s00 = fmaf(vj, tanh_approx(h0+e0), s00);
        s01 = fmaf(vj, tanh_approx(h0+e1), s01);
        s10 = fmaf(vj, tanh_approx(h1+e0), s10);
        s11 = fmaf(vj, tanh_approx(h1+e1), s11);
    }
    size_t base = ((size_t)b*256 + tt + ti)*256 + it + ii;
    out[base]       = s00; out[base+1]   = s01;
    out[base+256]   = s10; out[base+257] = s11;
}

// ---------------- host ----------------
#define TG_SMEM (4*128*STR_*2)

extern "C" void kernel_launch(void* const* d_in, const int* in_sizes, int n_in,
                              void* d_out, int out_size)
{
    const float* parts    = (const float*)d_in[0];
    const float* bin_info = (const float*)d_in[1];
    const int*   target   = (const int*)  d_in[2];
    const float* pe_W1 = (const float*)d_in[3];
    const float* pe_b1 = (const float*)d_in[4];
    const float* pe_W2 = (const float*)d_in[5];
    const float* pe_b2 = (const float*)d_in[6];
    const float* be_W1 = (const float*)d_in[7];
    const float* be_b1 = (const float*)d_in[8];
    const float* be_W2 = (const float*)d_in[9];
    const float* be_b2 = (const float*)d_in[10];
    const float* pos_emb = (const float*)d_in[11];
    const float* tr_Wqkv = (const float*)d_in[12];
    const float* tr_bqkv = (const float*)d_in[13];
    const float* tr_Wo   = (const float*)d_in[14];
    const float* tr_bo   = (const float*)d_in[15];
    const float* tr_ln1_g = (const float*)d_in[16];
    const float* tr_ln1_b = (const float*)d_in[17];
    const float* tr_ff_W1 = (const float*)d_in[18];
    const float* tr_ff_b1 = (const float*)d_in[19];
    const float* tr_ff_W2 = (const float*)d_in[20];
    const float* tr_ff_b2 = (const float*)d_in[21];
    const float* tr_ln2_g = (const float*)d_in[22];
    const float* tr_ln2_b = (const float*)d_in[23];
    const float* lstm_Wih = (const float*)d_in[24];
    const float* lstm_Whh = (const float*)d_in[25];
    const float* lstm_bih = (const float*)d_in[26];
    const float* lstm_bhh = (const float*)d_in[27];
    const float* ptr_W = (const float*)d_in[28];
    const float* ptr_b = (const float*)d_in[29];
    const float* ptr_v = (const float*)d_in[30];
    float* out = (float*)d_out;

    float *x_, *qkv_, *tmp_, *bb_, *ep_, *gin_, *hp_, *hbuf_;
    __half *whi_, *wlo_, *phi_, *plo_, *xhi_, *xlo_, *athi_, *atlo_;
    __half *ffhi_, *fflo_, *xihi_, *xilo_, *hahi_, *halo_;
    int* cnt_;
    cudaGetSymbolAddress((void**)&x_,    g_x);
    cudaGetSymbolAddress((void**)&qkv_,  g_qkv);
    cudaGetSymbolAddress((void**)&tmp_,  g_tmp);
    cudaGetSymbolAddress((void**)&bb_,   g_bb);
    cudaGetSymbolAddress((void**)&ep_,   g_eproj);
    cudaGetSymbolAddress((void**)&gin_,  g_gin);
    cudaGetSymbolAddress((void**)&hp_,   g_hp);
    cudaGetSymbolAddress((void**)&hbuf_, g_hbuf);
    cudaGetSymbolAddress((void**)&cnt_,  g_cnt);
    cudaGetSymbolAddress((void**)&whi_,  g_whi);
    cudaGetSymbolAddress((void**)&wlo_,  g_wlo);
    cudaGetSymbolAddress((void**)&phi_,  g_phi);
    cudaGetSymbolAddress((void**)&plo_,  g_plo);
    cudaGetSymbolAddress((void**)&xhi_,  g_xhi);
    cudaGetSymbolAddress((void**)&xlo_,  g_xlo);
    cudaGetSymbolAddress((void**)&athi_, g_athi);
    cudaGetSymbolAddress((void**)&atlo_, g_atlo);
    cudaGetSymbolAddress((void**)&ffhi_, g_ffhi);
    cudaGetSymbolAddress((void**)&fflo_, g_fflo);
    cudaGetSymbolAddress((void**)&xihi_, g_xihi);
    cudaGetSymbolAddress((void**)&xilo_, g_xilo);
    cudaGetSymbolAddress((void**)&hahi_, g_hahi);
    cudaGetSymbolAddress((void**)&halo_, g_halo);

    cudaFuncSetAttribute(attn_kernel,   cudaFuncAttributeMaxDynamicSharedMemorySize, 65536);
    cudaFuncSetAttribute(logits_kernel, cudaFuncAttributeMaxDynamicSharedMemorySize, 69632);
    cudaFuncSetAttribute(tgemm<1,1,16>, cudaFuncAttributeMaxDynamicSharedMemorySize, TG_SMEM);
    cudaFuncSetAttribute(tgemm<0,0,32>, cudaFuncAttributeMaxDynamicSharedMemorySize, TG_SMEM);
    cudaFuncSetAttribute(tgemm<1,1,32>, cudaFuncAttributeMaxDynamicSharedMemorySize, TG_SMEM);

    // weight + input splits
    split_kernel<<<8,    256>>>(pe_W1,    whi_+OFF_PEW1, wlo_+OFF_PEW1, 2048);
    split_kernel<<<64,   256>>>(pe_W2,    whi_+OFF_PEW2, wlo_+OFF_PEW2, 16384);
    split_kernel<<<2304, 256>>>(tr_Wqkv,  whi_+OFF_WQKV, wlo_+OFF_WQKV, 589824);
    split_kernel<<<768,  256>>>(tr_Wo,    whi_+OFF_WO,   wlo_+OFF_WO,   196608);
    split_kernel<<<1536, 256>>>(tr_ff_W1, whi_+OFF_FFW1, wlo_+OFF_FFW1, 393216);
    split_kernel<<<1536, 256>>>(tr_ff_W2, whi_+OFF_FFW2, wlo_+OFF_FFW2, 393216);
    split_kernel<<<1024, 256>>>(lstm_Wih, whi_+OFF_WIH,  wlo_+OFF_WIH,  262144);
    split_kernel<<<256,  256>>>(ptr_W,    whi_+OFF_PTRW, wlo_+OFF_PTRW, 65536);
    split_kernel<<<512,  256>>>(parts,    phi_, plo_, 131072);

    // encoders
    bin_enc_kernel<<<32, 64>>>(bin_info, be_W1, be_b1, be_W2, be_b2, bb_);
    tgemm<1,1,16><<<dim3(1,64), 256, TG_SMEM>>>(phi_, plo_, whi_+OFF_PEW1, wlo_+OFF_PEW1,
                                    pe_b1, nullptr, nullptr, athi_, atlo_, ROWS_, 128, 16);
    tgemm<0,0,32><<<dim3(1,64), 256, TG_SMEM>>>(athi_, atlo_, whi_+OFF_PEW2, wlo_+OFF_PEW2,
                                    pe_b2, nullptr, tmp_, nullptr, nullptr, ROWS_, 128, 128);
    concat_kernel<<<4096, 128>>>(tmp_, bb_, pos_emb, x_, xhi_, xlo_);

    // transformer layers
    for (int l = 0; l < 3; l++) {
        tgemm<0,0,32><<<dim3(6,64), 256, TG_SMEM>>>(xhi_, xlo_,
            whi_+OFF_WQKV + (size_t)l*196608, wlo_+OFF_WQKV + (size_t)l*196608,
            tr_bqkv + l*768, nullptr, qkv_, nullptr, nullptr, ROWS_, 768, 256);
        attn_kernel<<<256, 128, 65536>>>(qkv_, athi_, atlo_);
        tgemm<0,0,32><<<dim3(2,64), 256, TG_SMEM>>>(athi_, atlo_,
            whi_+OFF_WO + (size_t)l*65536, wlo_+OFF_WO + (size_t)l*65536,
            tr_bo + l*256, nullptr, tmp_, nullptr, nullptr, ROWS_, 256, 256);
        add_ln_kernel<<<1024, 256>>>(x_, tmp_, tr_ln1_g + l*256, tr_ln1_b + l*256,
                                     x_, xhi_, xlo_);
        tgemm<1,1,32><<<dim3(4,64), 256, TG_SMEM>>>(xhi_, xlo_,
            whi_+OFF_FFW1 + (size_t)l*131072, wlo_+OFF_FFW1 + (size_t)l*131072,
            tr_ff_b1 + l*512, nullptr, nullptr, ffhi_, fflo_, ROWS_, 512, 256);
        tgemm<0,0,32><<<dim3(2,64), 256, TG_SMEM>>>(ffhi_, fflo_,
            whi_+OFF_FFW2 + (size_t)l*131072, wlo_+OFF_FFW2 + (size_t)l*131072,
            tr_ff_b2 + l*256, nullptr, tmp_, nullptr, nullptr, ROWS_, 256, 512);
        add_ln_kernel<<<1024, 256>>>(x_, tmp_, tr_ln2_g + l*256, tr_ln2_b + l*256,
                                     x_, xhi_, xlo_);
    }

    // pointer decode
    tgemm<0,0,32><<<dim3(2,64), 256, TG_SMEM>>>(xhi_, xlo_, whi_+OFF_PTRW, wlo_+OFF_PTRW,
                                    ptr_b, nullptr, ep_, nullptr, nullptr, ROWS_, 256, 256);
    gather_kernel<<<2048, 256>>>(x_, target, xihi_, xilo_);
    tgemm<0,0,32><<<dim3(8,64), 256, TG_SMEM>>>(xihi_, xilo_, whi_+OFF_WIH, wlo_+OFF_WIH,
                                    lstm_bih, lstm_bhh, gin_, nullptr, nullptr, ROWS_, 1024, 256);
    lstm_init_kernel<<<32, 256>>>(cnt_);
    lstm_kernel<<<256, 256>>>(gin_, lstm_Whh, hahi_, halo_, hbuf_, cnt_);
    tgemm<0,0,32><<<dim3(2,64), 256, TG_SMEM>>>(hahi_, halo_, whi_+OFF_PTRW, wlo_+OFF_PTRW,
                                    ptr_b, nullptr, hp_, nullptr, nullptr, ROWS_, 256, 256);
    logits_kernel<<<dim3(8,8,32), 256, 69632>>>(hp_, ep_, ptr_v, out);
}